// round 2
// baseline (speedup 1.0000x reference)
#include <cuda_runtime.h>
#include <math.h>

#define DIN 1546
#define DH  128
#define DFF 512
#define NL  2

static const int NMAXC = 20000;
static const int EMAXC = 640000;

// ---------------- scratch (device globals; no allocation allowed) ----------
__device__ __align__(16) float g_x   [NMAXC * DIN];     // x buffer for layers >= 1
__device__ __align__(16) float g_qkv [NMAXC * 6 * DH];  // q|k|v|r|hi|hj
__device__ __align__(16) float g_scr [EMAXC];           // per-edge score -> p
__device__ __align__(16) float g_aggr[NMAXC * DH];
__device__ __align__(16) float g_ss  [NMAXC * DH];
__device__ __align__(16) float g_t   [NMAXC * DFF];
__device__ __align__(16) float g_ss2 [NMAXC * DH];
__device__ __align__(16) float g_h2  [NMAXC * DH];
__device__ int g_src[EMAXC];
__device__ int g_dst[EMAXC];
__device__ unsigned g_maxu;
__device__ float    g_Z;
__device__ int      g_is64;

// monotonic float<->uint encoding for atomicMax over signed floats
__device__ __forceinline__ unsigned fenc(float f) {
    unsigned u = __float_as_uint(f);
    return (u & 0x80000000u) ? ~u : (u | 0x80000000u);
}
__device__ __forceinline__ float fdec(unsigned u) {
    return __uint_as_float((u & 0x80000000u) ? (u ^ 0x80000000u) : ~u);
}

// ---------------- edge-index dtype probe + decode ---------------------------
// If underlying data is int64 (values < 2^31), every odd 32-bit word is 0.
__global__ void detect_idx_k(const int* __restrict__ raw, int nsamp)
{
    int i = blockIdx.x * blockDim.x + threadIdx.x;
    if (i < nsamp && raw[2 * i + 1] != 0) atomicExch(&g_is64, 0);
}

__global__ void decode_idx_k(int E, int N, const int* __restrict__ raw,
                             int* __restrict__ src, int* __restrict__ dst)
{
    int is64 = g_is64;
    for (int e = blockIdx.x * blockDim.x + threadIdx.x; e < E;
         e += gridDim.x * blockDim.x) {
        int s, d;
        if (is64) {
            s = raw[2 * (size_t)e];
            d = raw[2 * ((size_t)E + e)];
        } else {
            s = raw[e];
            d = raw[(size_t)E + e];
        }
        src[e] = min(max(s, 0), N - 1);
        dst[e] = min(max(d, 0), N - 1);
    }
}

// ---------------- generic tiled SGEMM: C = act(A@B + bias) -----------------
// A[M,K] lda, B[K,Nn] ldb, C[M,Nn] ldc. act: 0 none, 1 relu, 2 leaky(0.01)
__global__ void sgemm_k(int M, int Nn, int K,
                        const float* __restrict__ A, int lda,
                        const float* __restrict__ B, int ldb,
                        const float* __restrict__ bias,
                        float* __restrict__ C, int ldc, int act)
{
    __shared__ float As[16][68];
    __shared__ float Bs[16][64];
    const int row0 = blockIdx.y * 64;
    const int col0 = blockIdx.x * 64;
    const int tid  = threadIdx.x;           // 256 threads
    const int trow = (tid >> 4) << 2;       // (tid/16)*4
    const int tcol = (tid & 15) << 2;       // (tid%16)*4

    float acc[4][4];
#pragma unroll
    for (int i = 0; i < 4; i++)
#pragma unroll
        for (int j = 0; j < 4; j++) acc[i][j] = 0.f;

    for (int k0 = 0; k0 < K; k0 += 16) {
#pragma unroll
        for (int i = 0; i < 4; i++) {
            int idx = tid + i * 256;
            int ar = idx >> 4, ak = idx & 15;
            int gr = row0 + ar, gk = k0 + ak;
            As[ak][ar] = (gr < M && gk < K) ? A[(size_t)gr * lda + gk] : 0.f;
        }
#pragma unroll
        for (int i = 0; i < 4; i++) {
            int idx = tid + i * 256;
            int bk = idx >> 6, bc = idx & 63;
            int gk = k0 + bk, gc = col0 + bc;
            Bs[bk][bc] = (gk < K && gc < Nn) ? B[(size_t)gk * ldb + gc] : 0.f;
        }
        __syncthreads();
#pragma unroll
        for (int kk = 0; kk < 16; kk++) {
            float4 a = *(const float4*)&As[kk][trow];
            float4 b = *(const float4*)&Bs[kk][tcol];
            acc[0][0] += a.x * b.x; acc[0][1] += a.x * b.y; acc[0][2] += a.x * b.z; acc[0][3] += a.x * b.w;
            acc[1][0] += a.y * b.x; acc[1][1] += a.y * b.y; acc[1][2] += a.y * b.z; acc[1][3] += a.y * b.w;
            acc[2][0] += a.z * b.x; acc[2][1] += a.z * b.y; acc[2][2] += a.z * b.z; acc[2][3] += a.z * b.w;
            acc[3][0] += a.w * b.x; acc[3][1] += a.w * b.y; acc[3][2] += a.w * b.z; acc[3][3] += a.w * b.w;
        }
        __syncthreads();
    }

#pragma unroll
    for (int i = 0; i < 4; i++) {
        int r = row0 + trow + i;
        if (r >= M) continue;
#pragma unroll
        for (int j = 0; j < 4; j++) {
            int c = col0 + tcol + j;
            if (c >= Nn) continue;
            float v = acc[i][j] + (bias ? bias[c] : 0.f);
            if (act == 1) v = fmaxf(v, 0.f);
            else if (act == 2) v = v > 0.f ? v : 0.01f * v;
            C[(size_t)r * ldc + c] = v;
        }
    }
}

// ---------------- edge pass 1: score = dot(q[dst], k[src]); track global max
__global__ void edge_score_k(int E, const int* __restrict__ srcA,
                             const int* __restrict__ dstA,
                             const float* __restrict__ qkv,
                             float* __restrict__ score)
{
    int warp  = (blockIdx.x * blockDim.x + threadIdx.x) >> 5;
    int lane  = threadIdx.x & 31;
    int wloc  = threadIdx.x >> 5;
    __shared__ float sm[8];
    float d = -3.4e38f;
    if (warp < E) {
        int src = srcA[warp];
        int dst = dstA[warp];
        float4 q = *(const float4*)(qkv + (size_t)dst * 768 + lane * 4);
        float4 k = *(const float4*)(qkv + (size_t)src * 768 + 128 + lane * 4);
        d = q.x * k.x + q.y * k.y + q.z * k.z + q.w * k.w;
#pragma unroll
        for (int o = 16; o; o >>= 1) d += __shfl_xor_sync(0xffffffffu, d, o);
        if (lane == 0) score[warp] = d;
    }
    if (lane == 0) sm[wloc] = d;
    __syncthreads();
    if (threadIdx.x == 0) {
        float m = sm[0];
        int nw = blockDim.x >> 5;
        for (int i = 1; i < nw; i++) m = fmaxf(m, sm[i]);
        atomicMax(&g_maxu, fenc(m));
    }
}

// ---------------- edge pass 2: p = exp(s - max); Z = sum(p); store p in-place
__global__ void expsum_k(int E, float* __restrict__ score)
{
    float gmax = fdec(g_maxu);
    float s = 0.f;
    for (int i = blockIdx.x * blockDim.x + threadIdx.x; i < E;
         i += gridDim.x * blockDim.x) {
        float p = expf(score[i] - gmax);
        score[i] = p;
        s += p;
    }
#pragma unroll
    for (int o = 16; o; o >>= 1) s += __shfl_xor_sync(0xffffffffu, s, o);
    __shared__ float sm[8];
    int w = threadIdx.x >> 5, l = threadIdx.x & 31;
    if (l == 0) sm[w] = s;
    __syncthreads();
    if (threadIdx.x == 0) {
        float t = 0.f;
        int nw = blockDim.x >> 5;
        for (int i = 0; i < nw; i++) t += sm[i];
        atomicAdd(&g_Z, t);
    }
}

// ---------------- edge pass 3: msg = p * v[src] * sigmoid(ea + hi[src] + hj[dst])
// scatter-add into aggr[dst] (division by Z deferred to node kernel)
__global__ void edge_msg_k(int E, const int* __restrict__ srcA,
                           const int* __restrict__ dstA,
                           const float* __restrict__ qkv,
                           const float* __restrict__ eattr,
                           const float* __restrict__ score,
                           float* __restrict__ aggr)
{
    int warp = (blockIdx.x * blockDim.x + threadIdx.x) >> 5;
    int lane = threadIdx.x & 31;
    if (warp >= E) return;
    int src = srcA[warp];
    int dst = dstA[warp];
    float p = __ldg(score + warp);

    float4 v  = *(const float4*)(qkv + (size_t)src * 768 + 256 + lane * 4);
    float4 hi = *(const float4*)(qkv + (size_t)src * 768 + 512 + lane * 4);
    float4 hj = *(const float4*)(qkv + (size_t)dst * 768 + 640 + lane * 4);
    float4 ea = *(const float4*)(eattr + (size_t)warp * 128 + lane * 4);

    float m0 = p * v.x * (1.f / (1.f + expf(-(ea.x + hi.x + hj.x))));
    float m1 = p * v.y * (1.f / (1.f + expf(-(ea.y + hi.y + hj.y))));
    float m2 = p * v.z * (1.f / (1.f + expf(-(ea.z + hi.z + hj.z))));
    float m3 = p * v.w * (1.f / (1.f + expf(-(ea.w + hi.w + hj.w))));

    float* out = aggr + (size_t)dst * 128 + lane * 4;
    atomicAdd(out + 0, m0);
    atomicAdd(out + 1, m1);
    atomicAdd(out + 2, m2);
    atomicAdd(out + 3, m3);
}

// ---------------- node kernels: LayerNorm over 128 dims ---------------------
__device__ __forceinline__ void block_meanvar_128(float h, float& mean, float& var)
{
    float s = h, s2 = h * h;
#pragma unroll
    for (int o = 16; o; o >>= 1) {
        s  += __shfl_xor_sync(0xffffffffu, s, o);
        s2 += __shfl_xor_sync(0xffffffffu, s2, o);
    }
    __shared__ float sm[8];
    int w = threadIdx.x >> 5, l = threadIdx.x & 31;
    if (l == 0) { sm[w] = s; sm[4 + w] = s2; }
    __syncthreads();
    float ts  = sm[0] + sm[1] + sm[2] + sm[3];
    float ts2 = sm[4] + sm[5] + sm[6] + sm[7];
    mean = ts * (1.f / 128.f);
    var  = ts2 * (1.f / 128.f) - mean * mean;
}

// h = aggr/Z + r ; ss = LN(h)*g1 + be1
__global__ void node_ln1_k(const float* __restrict__ aggr,
                           const float* __restrict__ qkv,
                           const float* __restrict__ gam,
                           const float* __restrict__ bet,
                           float* __restrict__ out)
{
    int n = blockIdx.x, d = threadIdx.x;
    float h = aggr[(size_t)n * 128 + d] / g_Z + qkv[(size_t)n * 768 + 384 + d];
    float mean, var;
    block_meanvar_128(h, mean, var);
    out[(size_t)n * 128 + d] = (h - mean) * rsqrtf(var + 1e-5f) * gam[d] + bet[d];
}

// h2 = LN(ss + ss2)*g2 + be2
__global__ void node_ln2_k(const float* __restrict__ ss,
                           const float* __restrict__ ss2,
                           const float* __restrict__ gam,
                           const float* __restrict__ bet,
                           float* __restrict__ out)
{
    int n = blockIdx.x, d = threadIdx.x;
    float h = ss[(size_t)n * 128 + d] + ss2[(size_t)n * 128 + d];
    float mean, var;
    block_meanvar_128(h, mean, var);
    out[(size_t)n * 128 + d] = (h - mean) * rsqrtf(var + 1e-5f) * gam[d] + bet[d];
}

// ---------------- host orchestration ---------------------------------------
extern "C" void kernel_launch(void* const* d_in, const int* in_sizes, int n_in,
                              void* d_out, int out_size)
{
    const float* x_in  = (const float*)d_in[0];
    const int*   eiraw = (const int*)d_in[1];
    const float* eattr = (const float*)d_in[2];
    const float* Wq  = (const float*)d_in[3];
    const float* bq  = (const float*)d_in[4];
    const float* Wk  = (const float*)d_in[5];
    const float* bk  = (const float*)d_in[6];
    const float* Wv  = (const float*)d_in[7];
    const float* bv  = (const float*)d_in[8];
    const float* Wr  = (const float*)d_in[9];
    const float* br  = (const float*)d_in[10];
    const float* Whi = (const float*)d_in[11];
    const float* Whj = (const float*)d_in[12];
    const float* W1  = (const float*)d_in[13];
    const float* b1  = (const float*)d_in[14];
    const float* W2  = (const float*)d_in[15];
    const float* b2  = (const float*)d_in[16];
    const float* g1  = (const float*)d_in[17];
    const float* be1 = (const float*)d_in[18];
    const float* g2  = (const float*)d_in[19];
    const float* be2 = (const float*)d_in[20];
    const float* linW  = (const float*)d_in[21];
    const float* linb  = (const float*)d_in[22];
    const float* lin2W = (const float*)d_in[23];
    const float* lin2b = (const float*)d_in[24];

    const int N = in_sizes[0] / DIN;
    const int E = in_sizes[1] / 2;

    float *x_buf, *qkv, *score, *aggr, *ss, *tbuf, *ss2, *h2;
    int *srcA, *dstA;
    void* p;
    cudaGetSymbolAddress(&p, g_x);    x_buf = (float*)p;
    cudaGetSymbolAddress(&p, g_qkv);  qkv   = (float*)p;
    cudaGetSymbolAddress(&p, g_scr);  score = (float*)p;
    cudaGetSymbolAddress(&p, g_aggr); aggr  = (float*)p;
    cudaGetSymbolAddress(&p, g_ss);   ss    = (float*)p;
    cudaGetSymbolAddress(&p, g_t);    tbuf  = (float*)p;
    cudaGetSymbolAddress(&p, g_ss2);  ss2   = (float*)p;
    cudaGetSymbolAddress(&p, g_h2);   h2    = (float*)p;
    cudaGetSymbolAddress(&p, g_src);  srcA  = (int*)p;
    cudaGetSymbolAddress(&p, g_dst);  dstA  = (int*)p;
    void *maxu_p, *z_p, *is64_p;
    cudaGetSymbolAddress(&maxu_p, g_maxu);
    cudaGetSymbolAddress(&z_p, g_Z);
    cudaGetSymbolAddress(&is64_p, g_is64);

    // decode edge indices once (dtype-robust)
    cudaMemsetAsync(is64_p, 1, 4);
    int nsamp = E < 65536 ? E : 65536;
    detect_idx_k<<<(nsamp + 255) / 256, 256>>>(eiraw, nsamp);
    decode_idx_k<<<512, 256>>>(E, N, eiraw, srcA, dstA);

    const float* xcur = x_in;
    const dim3 blk(256);
    const int eblocks = (E * 32 + 255) / 256;

    for (int l = 0; l < NL; l++) {
        // fused input projections: q,k,v,r,hi,hj -> qkv[N,768]
        const float* Ws[6] = {Wq, Wk, Wv, Wr, Whi, Whj};
        const float* bs[6] = {bq, bk, bv, br, nullptr, nullptr};
        dim3 gproj((DH + 63) / 64, (N + 63) / 64);
        for (int j = 0; j < 6; j++) {
            const float* Bp = Ws[j] + (size_t)l * DIN * DH;
            const float* bp = bs[j] ? bs[j] + (size_t)l * DH : nullptr;
            sgemm_k<<<gproj, blk>>>(N, DH, DIN, xcur, DIN, Bp, DH, bp,
                                    qkv + j * DH, 6 * DH, 0);
        }

        cudaMemsetAsync(maxu_p, 0, 4);
        cudaMemsetAsync(z_p, 0, 4);
        cudaMemsetAsync(aggr, 0, (size_t)N * DH * sizeof(float));

        edge_score_k<<<eblocks, 256>>>(E, srcA, dstA, qkv, score);
        expsum_k<<<1024, 256>>>(E, score);
        edge_msg_k<<<eblocks, 256>>>(E, srcA, dstA, qkv, eattr, score, aggr);

        node_ln1_k<<<N, 128>>>(aggr, qkv, g1 + (size_t)l * DH, be1 + (size_t)l * DH, ss);

        // FFMLP
        dim3 gff1((DFF + 63) / 64, (N + 63) / 64);
        sgemm_k<<<gff1, blk>>>(N, DFF, DH, ss, DH,
                               W1 + (size_t)l * DH * DFF, DFF,
                               b1 + (size_t)l * DFF, tbuf, DFF, 1);
        dim3 gff2((DH + 63) / 64, (N + 63) / 64);
        sgemm_k<<<gff2, blk>>>(N, DH, DFF, tbuf, DFF,
                               W2 + (size_t)l * DFF * DH, DH,
                               b2 + (size_t)l * DH, ss2, DH, 0);

        node_ln2_k<<<N, 128>>>(ss, ss2, g2 + (size_t)l * DH, be2 + (size_t)l * DH, h2);

        // shared 128 -> 1546 projection
        dim3 glin((DIN + 63) / 64, (N + 63) / 64);
        sgemm_k<<<glin, blk>>>(N, DIN, DH, h2, DH, linW, DIN, linb, x_buf, DIN, 0);
        xcur = x_buf;
    }

    // final 1546 -> 128 with leaky relu
    dim3 gfin((DH + 63) / 64, (N + 63) / 64);
    sgemm_k<<<gfin, blk>>>(N, DH, DIN, xcur, DIN, lin2W, DH, lin2b,
                           (float*)d_out, DH, 2);
}

// round 3
// speedup vs baseline: 1.0701x; 1.0701x over previous
#include <cuda_runtime.h>
#include <math.h>

#define DIN 1546
#define DH  128
#define DFF 512
#define NL  2

static const int NMAXC = 20000;
static const int EMAXC = 640000;

// ---------------- scratch (device globals; no allocation allowed) ----------
__device__ __align__(16) float g_x    [NMAXC * DIN];
__device__ __align__(16) float g_qkv  [NMAXC * 6 * DH];
__device__ __align__(16) float g_scr  [EMAXC];
__device__ __align__(16) float g_aggr [NMAXC * DH];
__device__ __align__(16) float g_ss   [NMAXC * DH];
__device__ __align__(16) float g_t    [NMAXC * DFF];
__device__ __align__(16) float g_ss2  [NMAXC * DH];
__device__ __align__(16) float g_h2   [NMAXC * DH];
__device__ __align__(16) float g_wpack[NL * DIN * 6 * DH];  // per-layer [1546,768]
__device__ __align__(16) float g_bpack[NL * 6 * DH];
__device__ int g_src[EMAXC];
__device__ int g_dst[EMAXC];
__device__ unsigned g_maxu;
__device__ float    g_Z;
__device__ int      g_is64;

__device__ __forceinline__ unsigned fenc(float f) {
    unsigned u = __float_as_uint(f);
    return (u & 0x80000000u) ? ~u : (u | 0x80000000u);
}
__device__ __forceinline__ float fdec(unsigned u) {
    return __uint_as_float((u & 0x80000000u) ? (u ^ 0x80000000u) : ~u);
}

// ---------------- edge-index dtype probe + decode ---------------------------
__global__ void detect_idx_k(const int* __restrict__ raw, int nsamp)
{
    int i = blockIdx.x * blockDim.x + threadIdx.x;
    if (i < nsamp && raw[2 * i + 1] != 0) atomicExch(&g_is64, 0);
}

__global__ void decode_idx_k(int E, int N, const int* __restrict__ raw,
                             int* __restrict__ src, int* __restrict__ dst)
{
    int is64 = g_is64;
    for (int e = blockIdx.x * blockDim.x + threadIdx.x; e < E;
         e += gridDim.x * blockDim.x) {
        int s, d;
        if (is64) {
            s = raw[2 * (size_t)e];
            d = raw[2 * ((size_t)E + e)];
        } else {
            s = raw[e];
            d = raw[(size_t)E + e];
        }
        src[e] = min(max(s, 0), N - 1);
        dst[e] = min(max(d, 0), N - 1);
    }
}

// ---------------- weight/bias packing: [Wq|Wk|Wv|Wr|Whi|Whj] ----------------
__global__ void pack_w_k(const float* __restrict__ Wq, const float* __restrict__ Wk,
                         const float* __restrict__ Wv, const float* __restrict__ Wr,
                         const float* __restrict__ Whi, const float* __restrict__ Whj,
                         float* __restrict__ out)  // [NL][DIN][768]
{
    const float* Ws[6] = {Wq, Wk, Wv, Wr, Whi, Whj};
    size_t total = (size_t)NL * DIN * DH;
    for (size_t i = blockIdx.x * (size_t)blockDim.x + threadIdx.x; i < total;
         i += (size_t)gridDim.x * blockDim.x) {
        int c = i % DH;
        int k = (i / DH) % DIN;
        int l = i / ((size_t)DH * DIN);
        size_t obase = (size_t)l * DIN * 768 + (size_t)k * 768 + c;
        size_t ibase = (size_t)l * DIN * DH + (size_t)k * DH + c;
#pragma unroll
        for (int j = 0; j < 6; j++) out[obase + j * DH] = Ws[j][ibase];
    }
}

__global__ void pack_b_k(const float* __restrict__ bq, const float* __restrict__ bk,
                         const float* __restrict__ bv, const float* __restrict__ br,
                         float* __restrict__ out)  // [NL][768]
{
    int i = threadIdx.x + blockIdx.x * blockDim.x;  // 0 .. NL*768-1
    if (i >= NL * 768) return;
    int c = i % 768, l = i / 768;
    int j = c / DH, cc = c % DH;
    float v = 0.f;
    if (j == 0) v = bq[l * DH + cc];
    else if (j == 1) v = bk[l * DH + cc];
    else if (j == 2) v = bv[l * DH + cc];
    else if (j == 3) v = br[l * DH + cc];
    out[i] = v;
}

// ---------------- SGEMM 128x128 tile, 8x8 microtile, 256 threads ------------
// C[M,Nn] = act(A[M,K] @ B[K,Nn] + bias). act: 0 none, 1 relu, 2 leaky(0.01)
__global__ void __launch_bounds__(256)
sgemm128_k(int M, int Nn, int K,
           const float* __restrict__ A, int lda,
           const float* __restrict__ B, int ldb,
           const float* __restrict__ bias,
           float* __restrict__ C, int ldc, int act)
{
    __shared__ float As[8][132];
    __shared__ float Bs[8][132];

    const int row0 = blockIdx.y * 128;
    const int col0 = blockIdx.x * 128;
    const int tid  = threadIdx.x;
    const int tx   = tid & 15;       // 0..15
    const int ty   = tid >> 4;       // 0..15

    // A-load mapping: 128 rows x 8 k, 4 elems per thread along K
    const int l_ar = tid >> 1;            // 0..127
    const int l_ak = (tid & 1) * 4;       // 0 or 4
    // B-load mapping: 8 k x 128 cols, 4 elems per thread along N
    const int l_bk = tid >> 5;            // 0..7
    const int l_bc = (tid & 31) * 4;      // 0..124

    float acc[8][8];
#pragma unroll
    for (int i = 0; i < 8; i++)
#pragma unroll
        for (int j = 0; j < 8; j++) acc[i][j] = 0.f;

    const int gr = row0 + l_ar;
    const bool grok = gr < M;
    const float* Arow = A + (size_t)gr * lda;

    for (int k0 = 0; k0 < K; k0 += 8) {
#pragma unroll
        for (int u = 0; u < 4; u++) {
            int gk = k0 + l_ak + u;
            As[l_ak + u][l_ar] = (grok && gk < K) ? Arow[gk] : 0.f;
        }
        {
            int gk = k0 + l_bk;
            const float* Brow = B + (size_t)gk * ldb + col0 + l_bc;
            bool gkok = gk < K;
#pragma unroll
            for (int u = 0; u < 4; u++) {
                int gc = col0 + l_bc + u;
                Bs[l_bk][l_bc + u] = (gkok && gc < Nn) ? Brow[u] : 0.f;
            }
        }
        __syncthreads();

#pragma unroll
        for (int kk = 0; kk < 8; kk++) {
            float4 a0 = *(const float4*)&As[kk][ty * 4];
            float4 a1 = *(const float4*)&As[kk][ty * 4 + 64];
            float4 b0 = *(const float4*)&Bs[kk][tx * 4];
            float4 b1 = *(const float4*)&Bs[kk][tx * 4 + 64];
            float a[8] = {a0.x, a0.y, a0.z, a0.w, a1.x, a1.y, a1.z, a1.w};
            float b[8] = {b0.x, b0.y, b0.z, b0.w, b1.x, b1.y, b1.z, b1.w};
#pragma unroll
            for (int i = 0; i < 8; i++)
#pragma unroll
                for (int j = 0; j < 8; j++)
                    acc[i][j] += a[i] * b[j];
        }
        __syncthreads();
    }

    // epilogue
#pragma unroll
    for (int i = 0; i < 8; i++) {
        int r = row0 + ty * 4 + (i < 4 ? i : 60 + i);   // +64 for upper half
        if (r >= M) continue;
#pragma unroll
        for (int j = 0; j < 8; j++) {
            int c = col0 + tx * 4 + (j < 4 ? j : 60 + j);
            if (c >= Nn) continue;
            float v = acc[i][j] + (bias ? bias[c] : 0.f);
            if (act == 1) v = fmaxf(v, 0.f);
            else if (act == 2) v = v > 0.f ? v : 0.01f * v;
            C[(size_t)r * ldc + c] = v;
        }
    }
}

// ---------------- edge pass 1: score = dot(q[dst], k[src]); track global max
__global__ void edge_score_k(int E, const int* __restrict__ srcA,
                             const int* __restrict__ dstA,
                             const float* __restrict__ qkv,
                             float* __restrict__ score)
{
    int warp  = (blockIdx.x * blockDim.x + threadIdx.x) >> 5;
    int lane  = threadIdx.x & 31;
    int wloc  = threadIdx.x >> 5;
    __shared__ float sm[8];
    float d = -3.4e38f;
    if (warp < E) {
        int src = srcA[warp];
        int dst = dstA[warp];
        float4 q = *(const float4*)(qkv + (size_t)dst * 768 + lane * 4);
        float4 k = *(const float4*)(qkv + (size_t)src * 768 + 128 + lane * 4);
        d = q.x * k.x + q.y * k.y + q.z * k.z + q.w * k.w;
#pragma unroll
        for (int o = 16; o; o >>= 1) d += __shfl_xor_sync(0xffffffffu, d, o);
        if (lane == 0) score[warp] = d;
    }
    if (lane == 0) sm[wloc] = d;
    __syncthreads();
    if (threadIdx.x == 0) {
        float m = sm[0];
        int nw = blockDim.x >> 5;
        for (int i = 1; i < nw; i++) m = fmaxf(m, sm[i]);
        atomicMax(&g_maxu, fenc(m));
    }
}

// ---------------- edge pass 2: p = exp(s - max); Z = sum(p) ------------------
__global__ void expsum_k(int E, float* __restrict__ score)
{
    float gmax = fdec(g_maxu);
    float s = 0.f;
    for (int i = blockIdx.x * blockDim.x + threadIdx.x; i < E;
         i += gridDim.x * blockDim.x) {
        float p = expf(score[i] - gmax);
        score[i] = p;
        s += p;
    }
#pragma unroll
    for (int o = 16; o; o >>= 1) s += __shfl_xor_sync(0xffffffffu, s, o);
    __shared__ float sm[8];
    int w = threadIdx.x >> 5, l = threadIdx.x & 31;
    if (l == 0) sm[w] = s;
    __syncthreads();
    if (threadIdx.x == 0) {
        float t = 0.f;
        int nw = blockDim.x >> 5;
        for (int i = 0; i < nw; i++) t += sm[i];
        atomicAdd(&g_Z, t);
    }
}

// ---------------- edge pass 3: scatter messages ------------------------------
__global__ void edge_msg_k(int E, const int* __restrict__ srcA,
                           const int* __restrict__ dstA,
                           const float* __restrict__ qkv,
                           const float* __restrict__ eattr,
                           const float* __restrict__ score,
                           float* __restrict__ aggr)
{
    int warp = (blockIdx.x * blockDim.x + threadIdx.x) >> 5;
    int lane = threadIdx.x & 31;
    if (warp >= E) return;
    int src = srcA[warp];
    int dst = dstA[warp];
    float p = __ldg(score + warp);

    float4 v  = *(const float4*)(qkv + (size_t)src * 768 + 256 + lane * 4);
    float4 hi = *(const float4*)(qkv + (size_t)src * 768 + 512 + lane * 4);
    float4 hj = *(const float4*)(qkv + (size_t)dst * 768 + 640 + lane * 4);
    float4 ea = *(const float4*)(eattr + (size_t)warp * 128 + lane * 4);

    float m0 = p * v.x * (1.f / (1.f + expf(-(ea.x + hi.x + hj.x))));
    float m1 = p * v.y * (1.f / (1.f + expf(-(ea.y + hi.y + hj.y))));
    float m2 = p * v.z * (1.f / (1.f + expf(-(ea.z + hi.z + hj.z))));
    float m3 = p * v.w * (1.f / (1.f + expf(-(ea.w + hi.w + hj.w))));

    float* out = aggr + (size_t)dst * 128 + lane * 4;
    atomicAdd(out + 0, m0);
    atomicAdd(out + 1, m1);
    atomicAdd(out + 2, m2);
    atomicAdd(out + 3, m3);
}

// ---------------- node LayerNorm kernels -------------------------------------
__device__ __forceinline__ void block_meanvar_128(float h, float& mean, float& var)
{
    float s = h, s2 = h * h;
#pragma unroll
    for (int o = 16; o; o >>= 1) {
        s  += __shfl_xor_sync(0xffffffffu, s, o);
        s2 += __shfl_xor_sync(0xffffffffu, s2, o);
    }
    __shared__ float sm[8];
    int w = threadIdx.x >> 5, l = threadIdx.x & 31;
    if (l == 0) { sm[w] = s; sm[4 + w] = s2; }
    __syncthreads();
    float ts  = sm[0] + sm[1] + sm[2] + sm[3];
    float ts2 = sm[4] + sm[5] + sm[6] + sm[7];
    mean = ts * (1.f / 128.f);
    var  = ts2 * (1.f / 128.f) - mean * mean;
}

__global__ void node_ln1_k(const float* __restrict__ aggr,
                           const float* __restrict__ qkv,
                           const float* __restrict__ gam,
                           const float* __restrict__ bet,
                           float* __restrict__ out)
{
    int n = blockIdx.x, d = threadIdx.x;
    float h = aggr[(size_t)n * 128 + d] / g_Z + qkv[(size_t)n * 768 + 384 + d];
    float mean, var;
    block_meanvar_128(h, mean, var);
    out[(size_t)n * 128 + d] = (h - mean) * rsqrtf(var + 1e-5f) * gam[d] + bet[d];
}

__global__ void node_ln2_k(const float* __restrict__ ss,
                           const float* __restrict__ ss2,
                           const float* __restrict__ gam,
                           const float* __restrict__ bet,
                           float* __restrict__ out)
{
    int n = blockIdx.x, d = threadIdx.x;
    float h = ss[(size_t)n * 128 + d] + ss2[(size_t)n * 128 + d];
    float mean, var;
    block_meanvar_128(h, mean, var);
    out[(size_t)n * 128 + d] = (h - mean) * rsqrtf(var + 1e-5f) * gam[d] + bet[d];
}

// ---------------- host orchestration ---------------------------------------
extern "C" void kernel_launch(void* const* d_in, const int* in_sizes, int n_in,
                              void* d_out, int out_size)
{
    const float* x_in  = (const float*)d_in[0];
    const int*   eiraw = (const int*)d_in[1];
    const float* eattr = (const float*)d_in[2];
    const float* Wq  = (const float*)d_in[3];
    const float* bq  = (const float*)d_in[4];
    const float* Wk  = (const float*)d_in[5];
    const float* bk  = (const float*)d_in[6];
    const float* Wv  = (const float*)d_in[7];
    const float* bv  = (const float*)d_in[8];
    const float* Wr  = (const float*)d_in[9];
    const float* br  = (const float*)d_in[10];
    const float* Whi = (const float*)d_in[11];
    const float* Whj = (const float*)d_in[12];
    const float* W1  = (const float*)d_in[13];
    const float* b1  = (const float*)d_in[14];
    const float* W2  = (const float*)d_in[15];
    const float* b2  = (const float*)d_in[16];
    const float* g1  = (const float*)d_in[17];
    const float* be1 = (const float*)d_in[18];
    const float* g2  = (const float*)d_in[19];
    const float* be2 = (const float*)d_in[20];
    const float* linW  = (const float*)d_in[21];
    const float* linb  = (const float*)d_in[22];
    const float* lin2W = (const float*)d_in[23];
    const float* lin2b = (const float*)d_in[24];

    const int N = in_sizes[0] / DIN;
    const int E = in_sizes[1] / 2;

    float *x_buf, *qkv, *score, *aggr, *ss, *tbuf, *ss2, *h2, *wpack, *bpack;
    int *srcA, *dstA;
    void* p;
    cudaGetSymbolAddress(&p, g_x);     x_buf = (float*)p;
    cudaGetSymbolAddress(&p, g_qkv);   qkv   = (float*)p;
    cudaGetSymbolAddress(&p, g_scr);   score = (float*)p;
    cudaGetSymbolAddress(&p, g_aggr);  aggr  = (float*)p;
    cudaGetSymbolAddress(&p, g_ss);    ss    = (float*)p;
    cudaGetSymbolAddress(&p, g_t);     tbuf  = (float*)p;
    cudaGetSymbolAddress(&p, g_ss2);   ss2   = (float*)p;
    cudaGetSymbolAddress(&p, g_h2);    h2    = (float*)p;
    cudaGetSymbolAddress(&p, g_wpack); wpack = (float*)p;
    cudaGetSymbolAddress(&p, g_bpack); bpack = (float*)p;
    cudaGetSymbolAddress(&p, g_src);   srcA  = (int*)p;
    cudaGetSymbolAddress(&p, g_dst);   dstA  = (int*)p;
    void *maxu_p, *z_p, *is64_p;
    cudaGetSymbolAddress(&maxu_p, g_maxu);
    cudaGetSymbolAddress(&z_p, g_Z);
    cudaGetSymbolAddress(&is64_p, g_is64);

    // one-time per call: decode indices + pack weights
    cudaMemsetAsync(is64_p, 1, 4);
    int nsamp = E < 65536 ? E : 65536;
    detect_idx_k<<<(nsamp + 255) / 256, 256>>>(eiraw, nsamp);
    decode_idx_k<<<512, 256>>>(E, N, eiraw, srcA, dstA);
    pack_w_k<<<1024, 256>>>(Wq, Wk, Wv, Wr, Whi, Whj, wpack);
    pack_b_k<<<(NL * 768 + 255) / 256, 256>>>(bq, bk, bv, br, bpack);

    const float* xcur = x_in;
    const int eblocks = (E * 32 + 255) / 256;

    for (int l = 0; l < NL; l++) {
        // fused projection: x[N,1546] @ Wpack[1546,768] -> qkv[N,768]
        dim3 gproj((6 * DH + 127) / 128, (N + 127) / 128);
        sgemm128_k<<<gproj, 256>>>(N, 6 * DH, DIN, xcur, DIN,
                                   wpack + (size_t)l * DIN * 768, 768,
                                   bpack + (size_t)l * 768, qkv, 768, 0);

        cudaMemsetAsync(maxu_p, 0, 4);
        cudaMemsetAsync(z_p, 0, 4);
        cudaMemsetAsync(aggr, 0, (size_t)N * DH * sizeof(float));

        edge_score_k<<<eblocks, 256>>>(E, srcA, dstA, qkv, score);
        expsum_k<<<1024, 256>>>(E, score);
        edge_msg_k<<<eblocks, 256>>>(E, srcA, dstA, qkv, eattr, score, aggr);

        node_ln1_k<<<N, 128>>>(aggr, qkv, g1 + (size_t)l * DH, be1 + (size_t)l * DH, ss);

        // FFMLP
        dim3 gff1((DFF + 127) / 128, (N + 127) / 128);
        sgemm128_k<<<gff1, 256>>>(N, DFF, DH, ss, DH,
                                  W1 + (size_t)l * DH * DFF, DFF,
                                  b1 + (size_t)l * DFF, tbuf, DFF, 1);
        dim3 gff2((DH + 127) / 128, (N + 127) / 128);
        sgemm128_k<<<gff2, 256>>>(N, DH, DFF, tbuf, DFF,
                                  W2 + (size_t)l * DFF * DH, DH,
                                  b2 + (size_t)l * DH, ss2, DH, 0);

        node_ln2_k<<<N, 128>>>(ss, ss2, g2 + (size_t)l * DH, be2 + (size_t)l * DH, h2);

        // shared 128 -> 1546 projection
        dim3 glin((DIN + 127) / 128, (N + 127) / 128);
        sgemm128_k<<<glin, 256>>>(N, DIN, DH, h2, DH, linW, DIN, linb, x_buf, DIN, 0);
        xcur = x_buf;
    }

    // final 1546 -> 128 with leaky relu
    dim3 gfin((DH + 127) / 128, (N + 127) / 128);
    sgemm128_k<<<gfin, 256>>>(N, DH, DIN, xcur, DIN, lin2W, DH, lin2b,
                              (float*)d_out, DH, 2);
}

// round 4
// speedup vs baseline: 1.0850x; 1.0139x over previous
#include <cuda_runtime.h>
#include <math.h>

#define DIN 1546
#define DH  128
#define DFF 512
#define NL  2

static const int NMAXC = 20000;
static const int EMAXC = 640000;

// ---------------- scratch (device globals; no allocation allowed) ----------
__device__ __align__(16) float g_x    [NMAXC * DIN];
__device__ __align__(16) float g_qkv  [NMAXC * 6 * DH];
__device__ __align__(16) float g_scr  [EMAXC];
__device__ __align__(16) float g_aggr [NMAXC * DH];
__device__ __align__(16) float g_ss   [NMAXC * DH];
__device__ __align__(16) float g_t    [NMAXC * DFF];
__device__ __align__(16) float g_ss2  [NMAXC * DH];
__device__ __align__(16) float g_h2   [NMAXC * DH];
__device__ __align__(16) float g_wpack[NL * DIN * 6 * DH];
__device__ __align__(16) float g_bpack[NL * 6 * DH];
__device__ int g_src[EMAXC];
__device__ int g_dst[EMAXC];
__device__ unsigned g_maxu;
__device__ float    g_Z;
__device__ int      g_is64;

__device__ __forceinline__ unsigned fenc(float f) {
    unsigned u = __float_as_uint(f);
    return (u & 0x80000000u) ? ~u : (u | 0x80000000u);
}
__device__ __forceinline__ float fdec(unsigned u) {
    return __uint_as_float((u & 0x80000000u) ? (u ^ 0x80000000u) : ~u);
}

// ---------------- edge-index dtype probe + decode ---------------------------
__global__ void detect_idx_k(const int* __restrict__ raw, int nsamp)
{
    int i = blockIdx.x * blockDim.x + threadIdx.x;
    if (i < nsamp && raw[2 * i + 1] != 0) atomicExch(&g_is64, 0);
}

__global__ void decode_idx_k(int E, int N, const int* __restrict__ raw,
                             int* __restrict__ src, int* __restrict__ dst)
{
    int is64 = g_is64;
    for (int e = blockIdx.x * blockDim.x + threadIdx.x; e < E;
         e += gridDim.x * blockDim.x) {
        int s, d;
        if (is64) {
            s = raw[2 * (size_t)e];
            d = raw[2 * ((size_t)E + e)];
        } else {
            s = raw[e];
            d = raw[(size_t)E + e];
        }
        src[e] = min(max(s, 0), N - 1);
        dst[e] = min(max(d, 0), N - 1);
    }
}

// ---------------- weight/bias packing ----------------------------------------
__global__ void pack_w_k(const float* __restrict__ Wq, const float* __restrict__ Wk,
                         const float* __restrict__ Wv, const float* __restrict__ Wr,
                         const float* __restrict__ Whi, const float* __restrict__ Whj,
                         float* __restrict__ out)
{
    const float* Ws[6] = {Wq, Wk, Wv, Wr, Whi, Whj};
    size_t total = (size_t)NL * DIN * DH;
    for (size_t i = blockIdx.x * (size_t)blockDim.x + threadIdx.x; i < total;
         i += (size_t)gridDim.x * blockDim.x) {
        int c = i % DH;
        int k = (i / DH) % DIN;
        int l = i / ((size_t)DH * DIN);
        size_t obase = (size_t)l * DIN * 768 + (size_t)k * 768 + c;
        size_t ibase = (size_t)l * DIN * DH + (size_t)k * DH + c;
#pragma unroll
        for (int j = 0; j < 6; j++) out[obase + j * DH] = Ws[j][ibase];
    }
}

__global__ void pack_b_k(const float* __restrict__ bq, const float* __restrict__ bk,
                         const float* __restrict__ bv, const float* __restrict__ br,
                         float* __restrict__ out)
{
    int i = threadIdx.x + blockIdx.x * blockDim.x;
    if (i >= NL * 768) return;
    int c = i % 768, l = i / 768;
    int j = c / DH, cc = c % DH;
    float v = 0.f;
    if (j == 0) v = bq[l * DH + cc];
    else if (j == 1) v = bk[l * DH + cc];
    else if (j == 2) v = bv[l * DH + cc];
    else if (j == 3) v = br[l * DH + cc];
    out[i] = v;
}

// ---------------- pipelined SGEMM 128x128, kt=16, double-buffered ------------
__global__ void __launch_bounds__(256)
sgemm128_k(int M, int Nn, int K,
           const float* __restrict__ A, int lda,
           const float* __restrict__ B, int ldb,
           const float* __restrict__ bias,
           float* __restrict__ C, int ldc, int act)
{
    __shared__ float As[2][16][132];
    __shared__ float Bs[2][16][132];

    const int row0 = blockIdx.y * 128;
    const int col0 = blockIdx.x * 128;
    const int tid  = threadIdx.x;
    const int tx   = tid & 15;
    const int ty   = tid >> 4;

    // A-load: row l_ar, k l_ak..l_ak+7 (8 scalars per thread)
    const int l_ar = tid >> 1;
    const int l_ak = (tid & 1) * 8;
    // B-load: k-row l_bk, cols l_bc..l_bc+7
    const int l_bk = tid >> 4;
    const int l_bc = (tid & 15) * 8;

    float acc[8][8];
#pragma unroll
    for (int i = 0; i < 8; i++)
#pragma unroll
        for (int j = 0; j < 8; j++) acc[i][j] = 0.f;

    const int gr = row0 + l_ar;
    const bool grok = gr < M;
    const float* Arow = A + (size_t)gr * lda;
    const bool bcok = (col0 + l_bc + 7) < Nn;   // full 8-wide in range?

    // ---- load tile 0 directly into smem ----
#pragma unroll
    for (int u = 0; u < 8; u++) {
        int gk = l_ak + u;
        As[0][l_ak + u][l_ar] = (grok && gk < K) ? Arow[gk] : 0.f;
    }
    {
        const float* Brow = B + (size_t)l_bk * ldb + col0 + l_bc;
        bool gkok = l_bk < K;
#pragma unroll
        for (int u = 0; u < 8; u++) {
            bool ok = gkok && (bcok || (col0 + l_bc + u) < Nn);
            Bs[0][l_bk][l_bc + u] = ok ? Brow[u] : 0.f;
        }
    }
    __syncthreads();

    int buf = 0;
    for (int k0 = 0; k0 < K; k0 += 16) {
        const int knext = k0 + 16;
        float ra[8], rb[8];
        if (knext < K) {
            // prefetch next slice to registers (latency overlaps compute)
#pragma unroll
            for (int u = 0; u < 8; u++) {
                int gk = knext + l_ak + u;
                ra[u] = (grok && gk < K) ? Arow[gk] : 0.f;
            }
            int gk = knext + l_bk;
            const float* Brow = B + (size_t)gk * ldb + col0 + l_bc;
            bool gkok = gk < K;
#pragma unroll
            for (int u = 0; u < 8; u++) {
                bool ok = gkok && (bcok || (col0 + l_bc + u) < Nn);
                rb[u] = ok ? Brow[u] : 0.f;
            }
        }

        // ---- compute on current buffer ----
#pragma unroll
        for (int kk = 0; kk < 16; kk++) {
            float4 a0 = *(const float4*)&As[buf][kk][ty * 4];
            float4 a1 = *(const float4*)&As[buf][kk][ty * 4 + 64];
            float4 b0 = *(const float4*)&Bs[buf][kk][tx * 4];
            float4 b1 = *(const float4*)&Bs[buf][kk][tx * 4 + 64];
            float a[8] = {a0.x, a0.y, a0.z, a0.w, a1.x, a1.y, a1.z, a1.w};
            float b[8] = {b0.x, b0.y, b0.z, b0.w, b1.x, b1.y, b1.z, b1.w};
#pragma unroll
            for (int i = 0; i < 8; i++)
#pragma unroll
                for (int j = 0; j < 8; j++)
                    acc[i][j] += a[i] * b[j];
        }

        if (knext < K) {
            int nb = buf ^ 1;
#pragma unroll
            for (int u = 0; u < 8; u++) As[nb][l_ak + u][l_ar] = ra[u];
#pragma unroll
            for (int u = 0; u < 8; u++) Bs[nb][l_bk][l_bc + u] = rb[u];
            __syncthreads();
            buf = nb;
        }
    }

    // ---- epilogue ----
#pragma unroll
    for (int i = 0; i < 8; i++) {
        int r = row0 + ty * 4 + (i < 4 ? i : 60 + i);
        if (r >= M) continue;
#pragma unroll
        for (int j = 0; j < 8; j++) {
            int c = col0 + tx * 4 + (j < 4 ? j : 60 + j);
            if (c >= Nn) continue;
            float v = acc[i][j] + (bias ? bias[c] : 0.f);
            if (act == 1) v = fmaxf(v, 0.f);
            else if (act == 2) v = v > 0.f ? v : 0.01f * v;
            C[(size_t)r * ldc + c] = v;
        }
    }
}

// ---------------- edge pass 1 -------------------------------------------------
__global__ void edge_score_k(int E, const int* __restrict__ srcA,
                             const int* __restrict__ dstA,
                             const float* __restrict__ qkv,
                             float* __restrict__ score)
{
    int warp  = (blockIdx.x * blockDim.x + threadIdx.x) >> 5;
    int lane  = threadIdx.x & 31;
    int wloc  = threadIdx.x >> 5;
    __shared__ float sm[8];
    float d = -3.4e38f;
    if (warp < E) {
        int src = srcA[warp];
        int dst = dstA[warp];
        float4 q = *(const float4*)(qkv + (size_t)dst * 768 + lane * 4);
        float4 k = *(const float4*)(qkv + (size_t)src * 768 + 128 + lane * 4);
        d = q.x * k.x + q.y * k.y + q.z * k.z + q.w * k.w;
#pragma unroll
        for (int o = 16; o; o >>= 1) d += __shfl_xor_sync(0xffffffffu, d, o);
        if (lane == 0) score[warp] = d;
    }
    if (lane == 0) sm[wloc] = d;
    __syncthreads();
    if (threadIdx.x == 0) {
        float m = sm[0];
        int nw = blockDim.x >> 5;
        for (int i = 1; i < nw; i++) m = fmaxf(m, sm[i]);
        atomicMax(&g_maxu, fenc(m));
    }
}

// ---------------- edge pass 2 -------------------------------------------------
__global__ void expsum_k(int E, float* __restrict__ score)
{
    float gmax = fdec(g_maxu);
    float s = 0.f;
    for (int i = blockIdx.x * blockDim.x + threadIdx.x; i < E;
         i += gridDim.x * blockDim.x) {
        float p = expf(score[i] - gmax);
        score[i] = p;
        s += p;
    }
#pragma unroll
    for (int o = 16; o; o >>= 1) s += __shfl_xor_sync(0xffffffffu, s, o);
    __shared__ float sm[8];
    int w = threadIdx.x >> 5, l = threadIdx.x & 31;
    if (l == 0) sm[w] = s;
    __syncthreads();
    if (threadIdx.x == 0) {
        float t = 0.f;
        int nw = blockDim.x >> 5;
        for (int i = 0; i < nw; i++) t += sm[i];
        atomicAdd(&g_Z, t);
    }
}

// ---------------- edge pass 3 -------------------------------------------------
__global__ void edge_msg_k(int E, const int* __restrict__ srcA,
                           const int* __restrict__ dstA,
                           const float* __restrict__ qkv,
                           const float* __restrict__ eattr,
                           const float* __restrict__ score,
                           float* __restrict__ aggr)
{
    int warp = (blockIdx.x * blockDim.x + threadIdx.x) >> 5;
    int lane = threadIdx.x & 31;
    if (warp >= E) return;
    int src = srcA[warp];
    int dst = dstA[warp];
    float p = __ldg(score + warp);

    float4 v  = *(const float4*)(qkv + (size_t)src * 768 + 256 + lane * 4);
    float4 hi = *(const float4*)(qkv + (size_t)src * 768 + 512 + lane * 4);
    float4 hj = *(const float4*)(qkv + (size_t)dst * 768 + 640 + lane * 4);
    float4 ea = *(const float4*)(eattr + (size_t)warp * 128 + lane * 4);

    float m0 = p * v.x * (1.f / (1.f + expf(-(ea.x + hi.x + hj.x))));
    float m1 = p * v.y * (1.f / (1.f + expf(-(ea.y + hi.y + hj.y))));
    float m2 = p * v.z * (1.f / (1.f + expf(-(ea.z + hi.z + hj.z))));
    float m3 = p * v.w * (1.f / (1.f + expf(-(ea.w + hi.w + hj.w))));

    float* out = aggr + (size_t)dst * 128 + lane * 4;
    atomicAdd(out + 0, m0);
    atomicAdd(out + 1, m1);
    atomicAdd(out + 2, m2);
    atomicAdd(out + 3, m3);
}

// ---------------- node LayerNorm kernels ---------------------------------------
__device__ __forceinline__ void block_meanvar_128(float h, float& mean, float& var)
{
    float s = h, s2 = h * h;
#pragma unroll
    for (int o = 16; o; o >>= 1) {
        s  += __shfl_xor_sync(0xffffffffu, s, o);
        s2 += __shfl_xor_sync(0xffffffffu, s2, o);
    }
    __shared__ float sm[8];
    int w = threadIdx.x >> 5, l = threadIdx.x & 31;
    if (l == 0) { sm[w] = s; sm[4 + w] = s2; }
    __syncthreads();
    float ts  = sm[0] + sm[1] + sm[2] + sm[3];
    float ts2 = sm[4] + sm[5] + sm[6] + sm[7];
    mean = ts * (1.f / 128.f);
    var  = ts2 * (1.f / 128.f) - mean * mean;
}

__global__ void node_ln1_k(const float* __restrict__ aggr,
                           const float* __restrict__ qkv,
                           const float* __restrict__ gam,
                           const float* __restrict__ bet,
                           float* __restrict__ out)
{
    int n = blockIdx.x, d = threadIdx.x;
    float h = aggr[(size_t)n * 128 + d] / g_Z + qkv[(size_t)n * 768 + 384 + d];
    float mean, var;
    block_meanvar_128(h, mean, var);
    out[(size_t)n * 128 + d] = (h - mean) * rsqrtf(var + 1e-5f) * gam[d] + bet[d];
}

__global__ void node_ln2_k(const float* __restrict__ ss,
                           const float* __restrict__ ss2,
                           const float* __restrict__ gam,
                           const float* __restrict__ bet,
                           float* __restrict__ out)
{
    int n = blockIdx.x, d = threadIdx.x;
    float h = ss[(size_t)n * 128 + d] + ss2[(size_t)n * 128 + d];
    float mean, var;
    block_meanvar_128(h, mean, var);
    out[(size_t)n * 128 + d] = (h - mean) * rsqrtf(var + 1e-5f) * gam[d] + bet[d];
}

// ---------------- host orchestration ---------------------------------------
extern "C" void kernel_launch(void* const* d_in, const int* in_sizes, int n_in,
                              void* d_out, int out_size)
{
    const float* x_in  = (const float*)d_in[0];
    const int*   eiraw = (const int*)d_in[1];
    const float* eattr = (const float*)d_in[2];
    const float* Wq  = (const float*)d_in[3];
    const float* bq  = (const float*)d_in[4];
    const float* Wk  = (const float*)d_in[5];
    const float* bk  = (const float*)d_in[6];
    const float* Wv  = (const float*)d_in[7];
    const float* bv  = (const float*)d_in[8];
    const float* Wr  = (const float*)d_in[9];
    const float* br  = (const float*)d_in[10];
    const float* Whi = (const float*)d_in[11];
    const float* Whj = (const float*)d_in[12];
    const float* W1  = (const float*)d_in[13];
    const float* b1  = (const float*)d_in[14];
    const float* W2  = (const float*)d_in[15];
    const float* b2  = (const float*)d_in[16];
    const float* g1  = (const float*)d_in[17];
    const float* be1 = (const float*)d_in[18];
    const float* g2  = (const float*)d_in[19];
    const float* be2 = (const float*)d_in[20];
    const float* linW  = (const float*)d_in[21];
    const float* linb  = (const float*)d_in[22];
    const float* lin2W = (const float*)d_in[23];
    const float* lin2b = (const float*)d_in[24];

    const int N = in_sizes[0] / DIN;
    const int E = in_sizes[1] / 2;

    float *x_buf, *qkv, *score, *aggr, *ss, *tbuf, *ss2, *h2, *wpack, *bpack;
    int *srcA, *dstA;
    void* p;
    cudaGetSymbolAddress(&p, g_x);     x_buf = (float*)p;
    cudaGetSymbolAddress(&p, g_qkv);   qkv   = (float*)p;
    cudaGetSymbolAddress(&p, g_scr);   score = (float*)p;
    cudaGetSymbolAddress(&p, g_aggr);  aggr  = (float*)p;
    cudaGetSymbolAddress(&p, g_ss);    ss    = (float*)p;
    cudaGetSymbolAddress(&p, g_t);     tbuf  = (float*)p;
    cudaGetSymbolAddress(&p, g_ss2);   ss2   = (float*)p;
    cudaGetSymbolAddress(&p, g_h2);    h2    = (float*)p;
    cudaGetSymbolAddress(&p, g_wpack); wpack = (float*)p;
    cudaGetSymbolAddress(&p, g_bpack); bpack = (float*)p;
    cudaGetSymbolAddress(&p, g_src);   srcA  = (int*)p;
    cudaGetSymbolAddress(&p, g_dst);   dstA  = (int*)p;
    void *maxu_p, *z_p, *is64_p;
    cudaGetSymbolAddress(&maxu_p, g_maxu);
    cudaGetSymbolAddress(&z_p, g_Z);
    cudaGetSymbolAddress(&is64_p, g_is64);

    cudaMemsetAsync(is64_p, 1, 4);
    int nsamp = E < 65536 ? E : 65536;
    detect_idx_k<<<(nsamp + 255) / 256, 256>>>(eiraw, nsamp);
    decode_idx_k<<<512, 256>>>(E, N, eiraw, srcA, dstA);
    pack_w_k<<<1024, 256>>>(Wq, Wk, Wv, Wr, Whi, Whj, wpack);
    pack_b_k<<<(NL * 768 + 255) / 256, 256>>>(bq, bk, bv, br, bpack);

    const float* xcur = x_in;
    const int eblocks = (E * 32 + 255) / 256;

    for (int l = 0; l < NL; l++) {
        dim3 gproj((6 * DH + 127) / 128, (N + 127) / 128);
        sgemm128_k<<<gproj, 256>>>(N, 6 * DH, DIN, xcur, DIN,
                                   wpack + (size_t)l * DIN * 768, 768,
                                   bpack + (size_t)l * 768, qkv, 768, 0);

        cudaMemsetAsync(maxu_p, 0, 4);
        cudaMemsetAsync(z_p, 0, 4);
        cudaMemsetAsync(aggr, 0, (size_t)N * DH * sizeof(float));

        edge_score_k<<<eblocks, 256>>>(E, srcA, dstA, qkv, score);
        expsum_k<<<1024, 256>>>(E, score);
        edge_msg_k<<<eblocks, 256>>>(E, srcA, dstA, qkv, eattr, score, aggr);

        node_ln1_k<<<N, 128>>>(aggr, qkv, g1 + (size_t)l * DH, be1 + (size_t)l * DH, ss);

        dim3 gff1((DFF + 127) / 128, (N + 127) / 128);
        sgemm128_k<<<gff1, 256>>>(N, DFF, DH, ss, DH,
                                  W1 + (size_t)l * DH * DFF, DFF,
                                  b1 + (size_t)l * DFF, tbuf, DFF, 1);
        dim3 gff2((DH + 127) / 128, (N + 127) / 128);
        sgemm128_k<<<gff2, 256>>>(N, DH, DFF, tbuf, DFF,
                                  W2 + (size_t)l * DFF * DH, DH,
                                  b2 + (size_t)l * DH, ss2, DH, 0);

        node_ln2_k<<<N, 128>>>(ss, ss2, g2 + (size_t)l * DH, be2 + (size_t)l * DH, h2);

        dim3 glin((DIN + 127) / 128, (N + 127) / 128);
        sgemm128_k<<<glin, 256>>>(N, DIN, DH, h2, DH, linW, DIN, linb, x_buf, DIN, 0);
        xcur = x_buf;
    }

    dim3 gfin((DH + 127) / 128, (N + 127) / 128);
    sgemm128_k<<<gfin, 256>>>(N, DH, DIN, xcur, DIN, lin2W, DH, lin2b,
                              (float*)d_out, DH, 2);
}

// round 5
// speedup vs baseline: 1.1147x; 1.0274x over previous
#include <cuda_runtime.h>
#include <math.h>

#define DIN 1546
#define DH  128
#define DFF 512
#define NL  2

static const int NMAXC = 20000;
static const int EMAXC = 640000;

// ---------------- scratch (device globals; no allocation allowed) ----------
__device__ __align__(16) float g_x    [NMAXC * DIN];
__device__ __align__(16) float g_qkv  [NMAXC * 6 * DH];
__device__ __align__(16) float g_scr  [EMAXC];
__device__ __align__(16) float g_aggr [NMAXC * DH];
__device__ __align__(16) float g_ss   [NMAXC * DH];
__device__ __align__(16) float g_t    [NMAXC * DFF];
__device__ __align__(16) float g_ss2  [NMAXC * DH];
__device__ __align__(16) float g_h2   [NMAXC * DH];
__device__ __align__(16) float g_wpack[NL * DIN * 6 * DH];
__device__ __align__(16) float g_bpack[NL * 6 * DH];
__device__ int g_src[EMAXC];
__device__ int g_dst[EMAXC];
__device__ unsigned g_maxu;
__device__ float    g_Z;
__device__ int      g_is64;

__device__ __forceinline__ unsigned fenc(float f) {
    unsigned u = __float_as_uint(f);
    return (u & 0x80000000u) ? ~u : (u | 0x80000000u);
}
__device__ __forceinline__ float fdec(unsigned u) {
    return __uint_as_float((u & 0x80000000u) ? (u ^ 0x80000000u) : ~u);
}

// ---------------- edge-index dtype probe + decode ---------------------------
__global__ void detect_idx_k(const int* __restrict__ raw, int nsamp)
{
    int i = blockIdx.x * blockDim.x + threadIdx.x;
    if (i < nsamp && raw[2 * i + 1] != 0) atomicExch(&g_is64, 0);
}

__global__ void decode_idx_k(int E, int N, const int* __restrict__ raw,
                             int* __restrict__ src, int* __restrict__ dst)
{
    int is64 = g_is64;
    for (int e = blockIdx.x * blockDim.x + threadIdx.x; e < E;
         e += gridDim.x * blockDim.x) {
        int s, d;
        if (is64) {
            s = raw[2 * (size_t)e];
            d = raw[2 * ((size_t)E + e)];
        } else {
            s = raw[e];
            d = raw[(size_t)E + e];
        }
        src[e] = min(max(s, 0), N - 1);
        dst[e] = min(max(d, 0), N - 1);
    }
}

// ---------------- weight/bias packing ----------------------------------------
__global__ void pack_w_k(const float* __restrict__ Wq, const float* __restrict__ Wk,
                         const float* __restrict__ Wv, const float* __restrict__ Wr,
                         const float* __restrict__ Whi, const float* __restrict__ Whj,
                         float* __restrict__ out)
{
    const float* Ws[6] = {Wq, Wk, Wv, Wr, Whi, Whj};
    size_t total = (size_t)NL * DIN * DH;
    for (size_t i = blockIdx.x * (size_t)blockDim.x + threadIdx.x; i < total;
         i += (size_t)gridDim.x * blockDim.x) {
        int c = i % DH;
        int k = (i / DH) % DIN;
        int l = i / ((size_t)DH * DIN);
        size_t obase = (size_t)l * DIN * 768 + (size_t)k * 768 + c;
        size_t ibase = (size_t)l * DIN * DH + (size_t)k * DH + c;
#pragma unroll
        for (int j = 0; j < 6; j++) out[obase + j * DH] = Ws[j][ibase];
    }
}

__global__ void pack_b_k(const float* __restrict__ bq, const float* __restrict__ bk,
                         const float* __restrict__ bv, const float* __restrict__ br,
                         float* __restrict__ out)
{
    int i = threadIdx.x + blockIdx.x * blockDim.x;
    if (i >= NL * 768) return;
    int c = i % 768, l = i / 768;
    int j = c / DH, cc = c % DH;
    float v = 0.f;
    if (j == 0) v = bq[l * DH + cc];
    else if (j == 1) v = bk[l * DH + cc];
    else if (j == 2) v = bv[l * DH + cc];
    else if (j == 3) v = br[l * DH + cc];
    out[i] = v;
}

// ---------------- SGEMM 256x128 block tile, 16x8 microtile, kt=8, dbuf -------
// LDS bytes/FMA = 0.75 -> FMA-issue-bound (was 1.0 -> smem-crossbar-bound)
__global__ void __launch_bounds__(256)
sgemm256_k(int M, int Nn, int K,
           const float* __restrict__ A, int lda,
           const float* __restrict__ B, int ldb,
           const float* __restrict__ bias,
           float* __restrict__ C, int ldc, int act)
{
    __shared__ __align__(16) float As[2][8][260];
    __shared__ __align__(16) float Bs[2][8][132];

    const int row0 = blockIdx.y * 256;
    const int col0 = blockIdx.x * 128;
    const int tid  = threadIdx.x;
    const int tx   = tid & 15;       // col group 0..15
    const int ty   = tid >> 4;       // row group 0..15

    // A-load: one row per thread, 8 consecutive k's
    const int gr   = row0 + tid;
    const bool grok = gr < M;
    const float* Arow = A + (size_t)gr * lda;
    // B-load: k-row tid>>5, 4 cols
    const int l_bk = tid >> 5;
    const int l_bc = (tid & 31) * 4;
    const bool bcok = (col0 + l_bc + 3) < Nn;

    float acc[16][8];
#pragma unroll
    for (int i = 0; i < 16; i++)
#pragma unroll
        for (int j = 0; j < 8; j++) acc[i][j] = 0.f;

    // ---- slice 0 directly to smem ----
#pragma unroll
    for (int u = 0; u < 8; u++)
        As[0][u][tid] = (grok && u < K) ? Arow[u] : 0.f;
    {
        const float* Brow = B + (size_t)l_bk * ldb + col0 + l_bc;
#pragma unroll
        for (int u = 0; u < 4; u++) {
            bool ok = (l_bk < K) && (bcok || (col0 + l_bc + u) < Nn);
            Bs[0][l_bk][l_bc + u] = ok ? Brow[u] : 0.f;
        }
    }
    __syncthreads();

    int buf = 0;
    for (int k0 = 0; k0 < K; k0 += 8) {
        const int knext = k0 + 8;
        float ra[8], rb[4];
        if (knext < K) {
#pragma unroll
            for (int u = 0; u < 8; u++) {
                int gk = knext + u;
                ra[u] = (grok && gk < K) ? Arow[gk] : 0.f;
            }
            int gk = knext + l_bk;
            const float* Brow = B + (size_t)gk * ldb + col0 + l_bc;
            bool gkok = gk < K;
#pragma unroll
            for (int u = 0; u < 4; u++) {
                bool ok = gkok && (bcok || (col0 + l_bc + u) < Nn);
                rb[u] = ok ? Brow[u] : 0.f;
            }
        }

        // ---- compute 8 kk on current buffer ----
#pragma unroll
        for (int kk = 0; kk < 8; kk++) {
            float a[16], b[8];
            float4 t;
            t = *(const float4*)&As[buf][kk][ty * 4];
            a[0]=t.x; a[1]=t.y; a[2]=t.z; a[3]=t.w;
            t = *(const float4*)&As[buf][kk][ty * 4 + 64];
            a[4]=t.x; a[5]=t.y; a[6]=t.z; a[7]=t.w;
            t = *(const float4*)&As[buf][kk][ty * 4 + 128];
            a[8]=t.x; a[9]=t.y; a[10]=t.z; a[11]=t.w;
            t = *(const float4*)&As[buf][kk][ty * 4 + 192];
            a[12]=t.x; a[13]=t.y; a[14]=t.z; a[15]=t.w;
            t = *(const float4*)&Bs[buf][kk][tx * 4];
            b[0]=t.x; b[1]=t.y; b[2]=t.z; b[3]=t.w;
            t = *(const float4*)&Bs[buf][kk][tx * 4 + 64];
            b[4]=t.x; b[5]=t.y; b[6]=t.z; b[7]=t.w;
#pragma unroll
            for (int i = 0; i < 16; i++)
#pragma unroll
                for (int j = 0; j < 8; j++)
                    acc[i][j] += a[i] * b[j];
        }

        if (knext < K) {
            int nb = buf ^ 1;
#pragma unroll
            for (int u = 0; u < 8; u++) As[nb][u][tid] = ra[u];
#pragma unroll
            for (int u = 0; u < 4; u++) Bs[nb][l_bk][l_bc + u] = rb[u];
            __syncthreads();
            buf = nb;
        }
    }

    // ---- epilogue: rows ty*4+i + 64*ci, cols tx*4+j (+64) ----
#pragma unroll
    for (int ci = 0; ci < 4; ci++) {
#pragma unroll
        for (int i = 0; i < 4; i++) {
            int r = row0 + ci * 64 + ty * 4 + i;
            if (r >= M) continue;
#pragma unroll
            for (int j = 0; j < 8; j++) {
                int c = col0 + tx * 4 + (j < 4 ? j : 60 + j);
                if (c >= Nn) continue;
                float v = acc[ci * 4 + i][j] + (bias ? bias[c] : 0.f);
                if (act == 1) v = fmaxf(v, 0.f);
                else if (act == 2) v = v > 0.f ? v : 0.01f * v;
                C[(size_t)r * ldc + c] = v;
            }
        }
    }
}

// ---------------- edge pass 1 -------------------------------------------------
__global__ void edge_score_k(int E, const int* __restrict__ srcA,
                             const int* __restrict__ dstA,
                             const float* __restrict__ qkv,
                             float* __restrict__ score)
{
    int warp  = (blockIdx.x * blockDim.x + threadIdx.x) >> 5;
    int lane  = threadIdx.x & 31;
    int wloc  = threadIdx.x >> 5;
    __shared__ float sm[8];
    float d = -3.4e38f;
    if (warp < E) {
        int src = srcA[warp];
        int dst = dstA[warp];
        float4 q = *(const float4*)(qkv + (size_t)dst * 768 + lane * 4);
        float4 k = *(const float4*)(qkv + (size_t)src * 768 + 128 + lane * 4);
        d = q.x * k.x + q.y * k.y + q.z * k.z + q.w * k.w;
#pragma unroll
        for (int o = 16; o; o >>= 1) d += __shfl_xor_sync(0xffffffffu, d, o);
        if (lane == 0) score[warp] = d;
    }
    if (lane == 0) sm[wloc] = d;
    __syncthreads();
    if (threadIdx.x == 0) {
        float m = sm[0];
        int nw = blockDim.x >> 5;
        for (int i = 1; i < nw; i++) m = fmaxf(m, sm[i]);
        atomicMax(&g_maxu, fenc(m));
    }
}

// ---------------- edge pass 2 -------------------------------------------------
__global__ void expsum_k(int E, float* __restrict__ score)
{
    float gmax = fdec(g_maxu);
    float s = 0.f;
    for (int i = blockIdx.x * blockDim.x + threadIdx.x; i < E;
         i += gridDim.x * blockDim.x) {
        float p = expf(score[i] - gmax);
        score[i] = p;
        s += p;
    }
#pragma unroll
    for (int o = 16; o; o >>= 1) s += __shfl_xor_sync(0xffffffffu, s, o);
    __shared__ float sm[8];
    int w = threadIdx.x >> 5, l = threadIdx.x & 31;
    if (l == 0) sm[w] = s;
    __syncthreads();
    if (threadIdx.x == 0) {
        float t = 0.f;
        int nw = blockDim.x >> 5;
        for (int i = 0; i < nw; i++) t += sm[i];
        atomicAdd(&g_Z, t);
    }
}

// ---------------- edge pass 3 -------------------------------------------------
__global__ void edge_msg_k(int E, const int* __restrict__ srcA,
                           const int* __restrict__ dstA,
                           const float* __restrict__ qkv,
                           const float* __restrict__ eattr,
                           const float* __restrict__ score,
                           float* __restrict__ aggr)
{
    int warp = (blockIdx.x * blockDim.x + threadIdx.x) >> 5;
    int lane = threadIdx.x & 31;
    if (warp >= E) return;
    int src = srcA[warp];
    int dst = dstA[warp];
    float p = __ldg(score + warp);

    float4 v  = *(const float4*)(qkv + (size_t)src * 768 + 256 + lane * 4);
    float4 hi = *(const float4*)(qkv + (size_t)src * 768 + 512 + lane * 4);
    float4 hj = *(const float4*)(qkv + (size_t)dst * 768 + 640 + lane * 4);
    float4 ea = *(const float4*)(eattr + (size_t)warp * 128 + lane * 4);

    float m0 = p * v.x * (1.f / (1.f + expf(-(ea.x + hi.x + hj.x))));
    float m1 = p * v.y * (1.f / (1.f + expf(-(ea.y + hi.y + hj.y))));
    float m2 = p * v.z * (1.f / (1.f + expf(-(ea.z + hi.z + hj.z))));
    float m3 = p * v.w * (1.f / (1.f + expf(-(ea.w + hi.w + hj.w))));

    float* out = aggr + (size_t)dst * 128 + lane * 4;
    atomicAdd(out + 0, m0);
    atomicAdd(out + 1, m1);
    atomicAdd(out + 2, m2);
    atomicAdd(out + 3, m3);
}

// ---------------- node LayerNorm kernels ---------------------------------------
__device__ __forceinline__ void block_meanvar_128(float h, float& mean, float& var)
{
    float s = h, s2 = h * h;
#pragma unroll
    for (int o = 16; o; o >>= 1) {
        s  += __shfl_xor_sync(0xffffffffu, s, o);
        s2 += __shfl_xor_sync(0xffffffffu, s2, o);
    }
    __shared__ float sm[8];
    int w = threadIdx.x >> 5, l = threadIdx.x & 31;
    if (l == 0) { sm[w] = s; sm[4 + w] = s2; }
    __syncthreads();
    float ts  = sm[0] + sm[1] + sm[2] + sm[3];
    float ts2 = sm[4] + sm[5] + sm[6] + sm[7];
    mean = ts * (1.f / 128.f);
    var  = ts2 * (1.f / 128.f) - mean * mean;
}

__global__ void node_ln1_k(const float* __restrict__ aggr,
                           const float* __restrict__ qkv,
                           const float* __restrict__ gam,
                           const float* __restrict__ bet,
                           float* __restrict__ out)
{
    int n = blockIdx.x, d = threadIdx.x;
    float h = aggr[(size_t)n * 128 + d] / g_Z + qkv[(size_t)n * 768 + 384 + d];
    float mean, var;
    block_meanvar_128(h, mean, var);
    out[(size_t)n * 128 + d] = (h - mean) * rsqrtf(var + 1e-5f) * gam[d] + bet[d];
}

__global__ void node_ln2_k(const float* __restrict__ ss,
                           const float* __restrict__ ss2,
                           const float* __restrict__ gam,
                           const float* __restrict__ bet,
                           float* __restrict__ out)
{
    int n = blockIdx.x, d = threadIdx.x;
    float h = ss[(size_t)n * 128 + d] + ss2[(size_t)n * 128 + d];
    float mean, var;
    block_meanvar_128(h, mean, var);
    out[(size_t)n * 128 + d] = (h - mean) * rsqrtf(var + 1e-5f) * gam[d] + bet[d];
}

// ---------------- host orchestration ---------------------------------------
extern "C" void kernel_launch(void* const* d_in, const int* in_sizes, int n_in,
                              void* d_out, int out_size)
{
    const float* x_in  = (const float*)d_in[0];
    const int*   eiraw = (const int*)d_in[1];
    const float* eattr = (const float*)d_in[2];
    const float* Wq  = (const float*)d_in[3];
    const float* bq  = (const float*)d_in[4];
    const float* Wk  = (const float*)d_in[5];
    const float* bk  = (const float*)d_in[6];
    const float* Wv  = (const float*)d_in[7];
    const float* bv  = (const float*)d_in[8];
    const float* Wr  = (const float*)d_in[9];
    const float* br  = (const float*)d_in[10];
    const float* Whi = (const float*)d_in[11];
    const float* Whj = (const float*)d_in[12];
    const float* W1  = (const float*)d_in[13];
    const float* b1  = (const float*)d_in[14];
    const float* W2  = (const float*)d_in[15];
    const float* b2  = (const float*)d_in[16];
    const float* g1  = (const float*)d_in[17];
    const float* be1 = (const float*)d_in[18];
    const float* g2  = (const float*)d_in[19];
    const float* be2 = (const float*)d_in[20];
    const float* linW  = (const float*)d_in[21];
    const float* linb  = (const float*)d_in[22];
    const float* lin2W = (const float*)d_in[23];
    const float* lin2b = (const float*)d_in[24];

    const int N = in_sizes[0] / DIN;
    const int E = in_sizes[1] / 2;

    float *x_buf, *qkv, *score, *aggr, *ss, *tbuf, *ss2, *h2, *wpack, *bpack;
    int *srcA, *dstA;
    void* p;
    cudaGetSymbolAddress(&p, g_x);     x_buf = (float*)p;
    cudaGetSymbolAddress(&p, g_qkv);   qkv   = (float*)p;
    cudaGetSymbolAddress(&p, g_scr);   score = (float*)p;
    cudaGetSymbolAddress(&p, g_aggr);  aggr  = (float*)p;
    cudaGetSymbolAddress(&p, g_ss);    ss    = (float*)p;
    cudaGetSymbolAddress(&p, g_t);     tbuf  = (float*)p;
    cudaGetSymbolAddress(&p, g_ss2);   ss2   = (float*)p;
    cudaGetSymbolAddress(&p, g_h2);    h2    = (float*)p;
    cudaGetSymbolAddress(&p, g_wpack); wpack = (float*)p;
    cudaGetSymbolAddress(&p, g_bpack); bpack = (float*)p;
    cudaGetSymbolAddress(&p, g_src);   srcA  = (int*)p;
    cudaGetSymbolAddress(&p, g_dst);   dstA  = (int*)p;
    void *maxu_p, *z_p, *is64_p;
    cudaGetSymbolAddress(&maxu_p, g_maxu);
    cudaGetSymbolAddress(&z_p, g_Z);
    cudaGetSymbolAddress(&is64_p, g_is64);

    // prologue ordered so the 5th launch is the layer-0 projection GEMM
    // (ncu capture takes the 5th launch)
    cudaMemsetAsync(is64_p, 1, 4);                                      // 1
    int nsamp = E < 65536 ? E : 65536;
    detect_idx_k<<<(nsamp + 255) / 256, 256>>>(eiraw, nsamp);           // 2
    pack_w_k<<<1024, 256>>>(Wq, Wk, Wv, Wr, Whi, Whj, wpack);           // 3
    pack_b_k<<<(NL * 768 + 255) / 256, 256>>>(bq, bk, bv, br, bpack);   // 4

    const float* xcur = x_in;
    const int eblocks = (E * 32 + 255) / 256;
    bool decoded = false;

    for (int l = 0; l < NL; l++) {
        dim3 gproj((6 * DH + 127) / 128, (N + 255) / 256);
        sgemm256_k<<<gproj, 256>>>(N, 6 * DH, DIN, xcur, DIN,           // 5 (l=0)
                                   wpack + (size_t)l * DIN * 768, 768,
                                   bpack + (size_t)l * 768, qkv, 768, 0);

        if (!decoded) {
            decode_idx_k<<<512, 256>>>(E, N, eiraw, srcA, dstA);
            decoded = true;
        }
        cudaMemsetAsync(maxu_p, 0, 4);
        cudaMemsetAsync(z_p, 0, 4);
        cudaMemsetAsync(aggr, 0, (size_t)N * DH * sizeof(float));

        edge_score_k<<<eblocks, 256>>>(E, srcA, dstA, qkv, score);
        expsum_k<<<1024, 256>>>(E, score);
        edge_msg_k<<<eblocks, 256>>>(E, srcA, dstA, qkv, eattr, score, aggr);

        node_ln1_k<<<N, 128>>>(aggr, qkv, g1 + (size_t)l * DH, be1 + (size_t)l * DH, ss);

        dim3 gff1((DFF + 127) / 128, (N + 255) / 256);
        sgemm256_k<<<gff1, 256>>>(N, DFF, DH, ss, DH,
                                  W1 + (size_t)l * DH * DFF, DFF,
                                  b1 + (size_t)l * DFF, tbuf, DFF, 1);
        dim3 gff2((DH + 127) / 128, (N + 255) / 256);
        sgemm256_k<<<gff2, 256>>>(N, DH, DFF, tbuf, DFF,
                                  W2 + (size_t)l * DFF * DH, DH,
                                  b2 + (size_t)l * DH, ss2, DH, 0);

        node_ln2_k<<<N, 128>>>(ss, ss2, g2 + (size_t)l * DH, be2 + (size_t)l * DH, h2);

        dim3 glin((DIN + 127) / 128, (N + 255) / 256);
        sgemm256_k<<<glin, 256>>>(N, DIN, DH, h2, DH, linW, DIN, linb, x_buf, DIN, 0);
        xcur = x_buf;
    }

    dim3 gfin((DH + 127) / 128, (N + 255) / 256);
    sgemm256_k<<<gfin, 256>>>(N, DH, DIN, xcur, DIN, lin2W, DH, lin2b,
                              (float*)d_out, DH, 2);
}

// round 6
// speedup vs baseline: 1.6210x; 1.4541x over previous
#include <cuda_runtime.h>
#include <math.h>
#include <stdint.h>

#define DIN 1546
#define DH  128
#define DFF 512
#define NL  2

static const int NMAXC = 20000;
static const int EMAXC = 640000;

// ---------------- scratch (device globals; no allocation allowed) ----------
__device__ __align__(16) float g_x    [NMAXC * DIN];
__device__ __align__(16) float g_qkv  [NMAXC * 6 * DH];
__device__ __align__(16) float g_scr  [EMAXC];
__device__ __align__(16) float g_aggr [NMAXC * DH];
__device__ __align__(16) float g_ss   [NMAXC * DH];
__device__ __align__(16) float g_t    [NMAXC * DFF];
__device__ __align__(16) float g_ss2  [NMAXC * DH];
__device__ __align__(16) float g_h2   [NMAXC * DH];
__device__ __align__(16) float g_wpack[NL * DIN * 6 * DH];
__device__ __align__(16) float g_bpack[NL * 6 * DH];
__device__ int g_src[EMAXC];
__device__ int g_dst[EMAXC];
__device__ unsigned g_maxu;
__device__ float    g_Z;
__device__ int      g_is64;

__device__ __forceinline__ unsigned fenc(float f) {
    unsigned u = __float_as_uint(f);
    return (u & 0x80000000u) ? ~u : (u | 0x80000000u);
}
__device__ __forceinline__ float fdec(unsigned u) {
    return __uint_as_float((u & 0x80000000u) ? (u ^ 0x80000000u) : ~u);
}

// ---------------- tf32 helpers ------------------------------------------------
__device__ __forceinline__ uint32_t f2tf(float x) {
    uint32_t u;
    asm("cvt.rna.tf32.f32 %0, %1;" : "=r"(u) : "f"(x));
    return u;
}
__device__ __forceinline__ void split_tf32(float x, uint32_t& h, uint32_t& l) {
    h = f2tf(x);
    l = f2tf(x - __uint_as_float(h));
}
__device__ __forceinline__ void mma_tf32(float* c, const uint32_t* a, const uint32_t* b) {
    asm volatile(
        "mma.sync.aligned.m16n8k8.row.col.f32.tf32.tf32.f32 "
        "{%0,%1,%2,%3},{%4,%5,%6,%7},{%8,%9},{%0,%1,%2,%3};"
        : "+f"(c[0]), "+f"(c[1]), "+f"(c[2]), "+f"(c[3])
        : "r"(a[0]), "r"(a[1]), "r"(a[2]), "r"(a[3]), "r"(b[0]), "r"(b[1]));
}

// ---------------- edge-index dtype probe + decode ---------------------------
__global__ void detect_idx_k(const int* __restrict__ raw, int nsamp)
{
    int i = blockIdx.x * blockDim.x + threadIdx.x;
    if (i < nsamp && raw[2 * i + 1] != 0) atomicExch(&g_is64, 0);
}

__global__ void decode_idx_k(int E, int N, const int* __restrict__ raw,
                             int* __restrict__ src, int* __restrict__ dst)
{
    int is64 = g_is64;
    for (int e = blockIdx.x * blockDim.x + threadIdx.x; e < E;
         e += gridDim.x * blockDim.x) {
        int s, d;
        if (is64) {
            s = raw[2 * (size_t)e];
            d = raw[2 * ((size_t)E + e)];
        } else {
            s = raw[e];
            d = raw[(size_t)E + e];
        }
        src[e] = min(max(s, 0), N - 1);
        dst[e] = min(max(d, 0), N - 1);
    }
}

// ---------------- weight/bias packing ----------------------------------------
__global__ void pack_w_k(const float* __restrict__ Wq, const float* __restrict__ Wk,
                         const float* __restrict__ Wv, const float* __restrict__ Wr,
                         const float* __restrict__ Whi, const float* __restrict__ Whj,
                         float* __restrict__ out)
{
    const float* Ws[6] = {Wq, Wk, Wv, Wr, Whi, Whj};
    size_t total = (size_t)NL * DIN * DH;
    for (size_t i = blockIdx.x * (size_t)blockDim.x + threadIdx.x; i < total;
         i += (size_t)gridDim.x * blockDim.x) {
        int c = i % DH;
        int k = (i / DH) % DIN;
        int l = i / ((size_t)DH * DIN);
        size_t obase = (size_t)l * DIN * 768 + (size_t)k * 768 + c;
        size_t ibase = (size_t)l * DIN * DH + (size_t)k * DH + c;
#pragma unroll
        for (int j = 0; j < 6; j++) out[obase + j * DH] = Ws[j][ibase];
    }
}

__global__ void pack_b_k(const float* __restrict__ bq, const float* __restrict__ bk,
                         const float* __restrict__ bv, const float* __restrict__ br,
                         float* __restrict__ out)
{
    int i = threadIdx.x + blockIdx.x * blockDim.x;
    if (i >= NL * 768) return;
    int c = i % 768, l = i / 768;
    int j = c / DH, cc = c % DH;
    float v = 0.f;
    if (j == 0) v = bq[l * DH + cc];
    else if (j == 1) v = bk[l * DH + cc];
    else if (j == 2) v = bv[l * DH + cc];
    else if (j == 3) v = br[l * DH + cc];
    out[i] = v;
}

// ---------------- tensor-core GEMM: 3xTF32 split, BM=256 BN=128 BK=8 ---------
// 8 warps (4x2), warp tile 64x64 via m16n8k8. Fragment-layout smem,
// double-buffered, register prefetch. act: 0 none, 1 relu, 2 leaky(0.01)
__global__ void __launch_bounds__(256, 1)
mma_gemm_k(int M, int Nn, int K,
           const float* __restrict__ A, int lda,
           const float* __restrict__ B, int ldb,
           const float* __restrict__ bias,
           float* __restrict__ C, int ldc, int act)
{
    // [buf][split][tile][lane][reg]
    __shared__ __align__(16) uint32_t Asf[2][2][16][32][4];  // 32 KB
    __shared__ __align__(16) uint32_t Bsf[2][2][16][32][2];  // 16 KB

    const int tid  = threadIdx.x;
    const int lane = tid & 31;
    const int wid  = tid >> 5;
    const int g    = lane >> 2;   // group 0..7
    const int tig  = lane & 3;    // 0..3
    const int warp_m = wid & 3;   // 0..3  (64 rows each)
    const int warp_n = wid >> 2;  // 0..1  (64 cols each)
    const int row0 = blockIdx.y * 256;
    const int col0 = blockIdx.x * 128;

    float acc[4][8][4];
#pragma unroll
    for (int m = 0; m < 4; m++)
#pragma unroll
        for (int n = 0; n < 8; n++)
#pragma unroll
            for (int r = 0; r < 4; r++) acc[m][n][r] = 0.f;

    float pa[2][4], pb[2][2];

    // load one BK=8 slice (global -> regs), fragment-indexed
    auto load_regs = [&](int k0) {
#pragma unroll
        for (int i = 0; i < 2; i++) {
            int mt = wid * 2 + i;   // A tile 16 rows
#pragma unroll
            for (int r = 0; r < 4; r++) {
                int rr = row0 + mt * 16 + g + 8 * (r & 1);
                int cc = k0 + tig + 4 * (r >> 1);
                pa[i][r] = (rr < M && cc < K) ? A[(size_t)rr * lda + cc] : 0.f;
            }
        }
#pragma unroll
        for (int i = 0; i < 2; i++) {
            int nt = wid * 2 + i;   // B tile 8 cols
#pragma unroll
            for (int r = 0; r < 2; r++) {
                int kk = k0 + tig + 4 * r;
                int cc = col0 + nt * 8 + g;
                pb[i][r] = (kk < K && cc < Nn) ? B[(size_t)kk * ldb + cc] : 0.f;
            }
        }
    };

    // split regs -> smem fragments (STS.128 / STS.64, conflict-free)
    auto store_smem = [&](int buf) {
#pragma unroll
        for (int i = 0; i < 2; i++) {
            int mt = wid * 2 + i;
            uint4 h, l;
            split_tf32(pa[i][0], h.x, l.x);
            split_tf32(pa[i][1], h.y, l.y);
            split_tf32(pa[i][2], h.z, l.z);
            split_tf32(pa[i][3], h.w, l.w);
            *(uint4*)&Asf[buf][0][mt][lane][0] = h;
            *(uint4*)&Asf[buf][1][mt][lane][0] = l;
        }
#pragma unroll
        for (int i = 0; i < 2; i++) {
            int nt = wid * 2 + i;
            uint2 h, l;
            split_tf32(pb[i][0], h.x, l.x);
            split_tf32(pb[i][1], h.y, l.y);
            *(uint2*)&Bsf[buf][0][nt][lane][0] = h;
            *(uint2*)&Bsf[buf][1][nt][lane][0] = l;
        }
    };

    auto compute = [&](int buf) {
        uint32_t ah[4][4], al[4][4];
#pragma unroll
        for (int m = 0; m < 4; m++) {
            int mt = warp_m * 4 + m;
            uint4 t = *(const uint4*)&Asf[buf][0][mt][lane][0];
            ah[m][0] = t.x; ah[m][1] = t.y; ah[m][2] = t.z; ah[m][3] = t.w;
            uint4 u = *(const uint4*)&Asf[buf][1][mt][lane][0];
            al[m][0] = u.x; al[m][1] = u.y; al[m][2] = u.z; al[m][3] = u.w;
        }
#pragma unroll
        for (int n = 0; n < 8; n++) {
            int nt = warp_n * 8 + n;
            uint32_t bh[2], bl[2];
            uint2 t = *(const uint2*)&Bsf[buf][0][nt][lane][0];
            bh[0] = t.x; bh[1] = t.y;
            uint2 u = *(const uint2*)&Bsf[buf][1][nt][lane][0];
            bl[0] = u.x; bl[1] = u.y;
#pragma unroll
            for (int m = 0; m < 4; m++) {
                mma_tf32(acc[m][n], ah[m], bh);
                mma_tf32(acc[m][n], ah[m], bl);
                mma_tf32(acc[m][n], al[m], bh);
            }
        }
    };

    load_regs(0);
    store_smem(0);
    __syncthreads();

    int buf = 0;
    for (int k0 = 0; k0 < K; k0 += 8) {
        int kn = k0 + 8;
        bool more = kn < K;
        if (more) load_regs(kn);
        compute(buf);
        if (more) {
            store_smem(buf ^ 1);
            __syncthreads();
            buf ^= 1;
        }
    }

    // epilogue: c0(g, 2tig) c1(g, 2tig+1) c2(g+8, 2tig) c3(g+8, 2tig+1)
#pragma unroll
    for (int m = 0; m < 4; m++) {
        int rb = row0 + warp_m * 64 + m * 16 + g;
#pragma unroll
        for (int n = 0; n < 8; n++) {
            int cb = col0 + warp_n * 64 + n * 8 + tig * 2;
#pragma unroll
            for (int h = 0; h < 2; h++) {      // row half: +0 / +8
                int rr = rb + h * 8;
                if (rr >= M) continue;
#pragma unroll
                for (int q = 0; q < 2; q++) {  // col: +0 / +1
                    int cc = cb + q;
                    if (cc >= Nn) continue;
                    float v = acc[m][n][h * 2 + q] + (bias ? bias[cc] : 0.f);
                    if (act == 1) v = fmaxf(v, 0.f);
                    else if (act == 2) v = v > 0.f ? v : 0.01f * v;
                    C[(size_t)rr * ldc + cc] = v;
                }
            }
        }
    }
}

// ---------------- edge pass 1 -------------------------------------------------
__global__ void edge_score_k(int E, const int* __restrict__ srcA,
                             const int* __restrict__ dstA,
                             const float* __restrict__ qkv,
                             float* __restrict__ score)
{
    int warp  = (blockIdx.x * blockDim.x + threadIdx.x) >> 5;
    int lane  = threadIdx.x & 31;
    int wloc  = threadIdx.x >> 5;
    __shared__ float sm[8];
    float d = -3.4e38f;
    if (warp < E) {
        int src = srcA[warp];
        int dst = dstA[warp];
        float4 q = *(const float4*)(qkv + (size_t)dst * 768 + lane * 4);
        float4 k = *(const float4*)(qkv + (size_t)src * 768 + 128 + lane * 4);
        d = q.x * k.x + q.y * k.y + q.z * k.z + q.w * k.w;
#pragma unroll
        for (int o = 16; o; o >>= 1) d += __shfl_xor_sync(0xffffffffu, d, o);
        if (lane == 0) score[warp] = d;
    }
    if (lane == 0) sm[wloc] = d;
    __syncthreads();
    if (threadIdx.x == 0) {
        float m = sm[0];
        int nw = blockDim.x >> 5;
        for (int i = 1; i < nw; i++) m = fmaxf(m, sm[i]);
        atomicMax(&g_maxu, fenc(m));
    }
}

// ---------------- edge pass 2 -------------------------------------------------
__global__ void expsum_k(int E, float* __restrict__ score)
{
    float gmax = fdec(g_maxu);
    float s = 0.f;
    for (int i = blockIdx.x * blockDim.x + threadIdx.x; i < E;
         i += gridDim.x * blockDim.x) {
        float p = expf(score[i] - gmax);
        score[i] = p;
        s += p;
    }
#pragma unroll
    for (int o = 16; o; o >>= 1) s += __shfl_xor_sync(0xffffffffu, s, o);
    __shared__ float sm[8];
    int w = threadIdx.x >> 5, l = threadIdx.x & 31;
    if (l == 0) sm[w] = s;
    __syncthreads();
    if (threadIdx.x == 0) {
        float t = 0.f;
        int nw = blockDim.x >> 5;
        for (int i = 0; i < nw; i++) t += sm[i];
        atomicAdd(&g_Z, t);
    }
}

// ---------------- edge pass 3 -------------------------------------------------
__global__ void edge_msg_k(int E, const int* __restrict__ srcA,
                           const int* __restrict__ dstA,
                           const float* __restrict__ qkv,
                           const float* __restrict__ eattr,
                           const float* __restrict__ score,
                           float* __restrict__ aggr)
{
    int warp = (blockIdx.x * blockDim.x + threadIdx.x) >> 5;
    int lane = threadIdx.x & 31;
    if (warp >= E) return;
    int src = srcA[warp];
    int dst = dstA[warp];
    float p = __ldg(score + warp);

    float4 v  = *(const float4*)(qkv + (size_t)src * 768 + 256 + lane * 4);
    float4 hi = *(const float4*)(qkv + (size_t)src * 768 + 512 + lane * 4);
    float4 hj = *(const float4*)(qkv + (size_t)dst * 768 + 640 + lane * 4);
    float4 ea = *(const float4*)(eattr + (size_t)warp * 128 + lane * 4);

    float m0 = p * v.x * (1.f / (1.f + expf(-(ea.x + hi.x + hj.x))));
    float m1 = p * v.y * (1.f / (1.f + expf(-(ea.y + hi.y + hj.y))));
    float m2 = p * v.z * (1.f / (1.f + expf(-(ea.z + hi.z + hj.z))));
    float m3 = p * v.w * (1.f / (1.f + expf(-(ea.w + hi.w + hj.w))));

    float* out = aggr + (size_t)dst * 128 + lane * 4;
    atomicAdd(out + 0, m0);
    atomicAdd(out + 1, m1);
    atomicAdd(out + 2, m2);
    atomicAdd(out + 3, m3);
}

// ---------------- node LayerNorm kernels ---------------------------------------
__device__ __forceinline__ void block_meanvar_128(float h, float& mean, float& var)
{
    float s = h, s2 = h * h;
#pragma unroll
    for (int o = 16; o; o >>= 1) {
        s  += __shfl_xor_sync(0xffffffffu, s, o);
        s2 += __shfl_xor_sync(0xffffffffu, s2, o);
    }
    __shared__ float sm[8];
    int w = threadIdx.x >> 5, l = threadIdx.x & 31;
    if (l == 0) { sm[w] = s; sm[4 + w] = s2; }
    __syncthreads();
    float ts  = sm[0] + sm[1] + sm[2] + sm[3];
    float ts2 = sm[4] + sm[5] + sm[6] + sm[7];
    mean = ts * (1.f / 128.f);
    var  = ts2 * (1.f / 128.f) - mean * mean;
}

__global__ void node_ln1_k(const float* __restrict__ aggr,
                           const float* __restrict__ qkv,
                           const float* __restrict__ gam,
                           const float* __restrict__ bet,
                           float* __restrict__ out)
{
    int n = blockIdx.x, d = threadIdx.x;
    float h = aggr[(size_t)n * 128 + d] / g_Z + qkv[(size_t)n * 768 + 384 + d];
    float mean, var;
    block_meanvar_128(h, mean, var);
    out[(size_t)n * 128 + d] = (h - mean) * rsqrtf(var + 1e-5f) * gam[d] + bet[d];
}

__global__ void node_ln2_k(const float* __restrict__ ss,
                           const float* __restrict__ ss2,
                           const float* __restrict__ gam,
                           const float* __restrict__ bet,
                           float* __restrict__ out)
{
    int n = blockIdx.x, d = threadIdx.x;
    float h = ss[(size_t)n * 128 + d] + ss2[(size_t)n * 128 + d];
    float mean, var;
    block_meanvar_128(h, mean, var);
    out[(size_t)n * 128 + d] = (h - mean) * rsqrtf(var + 1e-5f) * gam[d] + bet[d];
}

// ---------------- host orchestration ---------------------------------------
extern "C" void kernel_launch(void* const* d_in, const int* in_sizes, int n_in,
                              void* d_out, int out_size)
{
    const float* x_in  = (const float*)d_in[0];
    const int*   eiraw = (const int*)d_in[1];
    const float* eattr = (const float*)d_in[2];
    const float* Wq  = (const float*)d_in[3];
    const float* bq  = (const float*)d_in[4];
    const float* Wk  = (const float*)d_in[5];
    const float* bk  = (const float*)d_in[6];
    const float* Wv  = (const float*)d_in[7];
    const float* bv  = (const float*)d_in[8];
    const float* Wr  = (const float*)d_in[9];
    const float* br  = (const float*)d_in[10];
    const float* Whi = (const float*)d_in[11];
    const float* Whj = (const float*)d_in[12];
    const float* W1  = (const float*)d_in[13];
    const float* b1  = (const float*)d_in[14];
    const float* W2  = (const float*)d_in[15];
    const float* b2  = (const float*)d_in[16];
    const float* g1  = (const float*)d_in[17];
    const float* be1 = (const float*)d_in[18];
    const float* g2  = (const float*)d_in[19];
    const float* be2 = (const float*)d_in[20];
    const float* linW  = (const float*)d_in[21];
    const float* linb  = (const float*)d_in[22];
    const float* lin2W = (const float*)d_in[23];
    const float* lin2b = (const float*)d_in[24];

    const int N = in_sizes[0] / DIN;
    const int E = in_sizes[1] / 2;

    float *x_buf, *qkv, *score, *aggr, *ss, *tbuf, *ss2, *h2, *wpack, *bpack;
    int *srcA, *dstA;
    void* p;
    cudaGetSymbolAddress(&p, g_x);     x_buf = (float*)p;
    cudaGetSymbolAddress(&p, g_qkv);   qkv   = (float*)p;
    cudaGetSymbolAddress(&p, g_scr);   score = (float*)p;
    cudaGetSymbolAddress(&p, g_aggr);  aggr  = (float*)p;
    cudaGetSymbolAddress(&p, g_ss);    ss    = (float*)p;
    cudaGetSymbolAddress(&p, g_t);     tbuf  = (float*)p;
    cudaGetSymbolAddress(&p, g_ss2);   ss2   = (float*)p;
    cudaGetSymbolAddress(&p, g_h2);    h2    = (float*)p;
    cudaGetSymbolAddress(&p, g_wpack); wpack = (float*)p;
    cudaGetSymbolAddress(&p, g_bpack); bpack = (float*)p;
    cudaGetSymbolAddress(&p, g_src);   srcA  = (int*)p;
    cudaGetSymbolAddress(&p, g_dst);   dstA  = (int*)p;
    void *maxu_p, *z_p, *is64_p;
    cudaGetSymbolAddress(&maxu_p, g_maxu);
    cudaGetSymbolAddress(&z_p, g_Z);
    cudaGetSymbolAddress(&is64_p, g_is64);

    // prologue ordered so the 5th launch is the layer-0 projection GEMM
    cudaMemsetAsync(is64_p, 1, 4);                                      // 1
    int nsamp = E < 65536 ? E : 65536;
    detect_idx_k<<<(nsamp + 255) / 256, 256>>>(eiraw, nsamp);           // 2
    pack_w_k<<<1024, 256>>>(Wq, Wk, Wv, Wr, Whi, Whj, wpack);           // 3
    pack_b_k<<<(NL * 768 + 255) / 256, 256>>>(bq, bk, bv, br, bpack);   // 4

    const float* xcur = x_in;
    const int eblocks = (E * 32 + 255) / 256;
    bool decoded = false;

    for (int l = 0; l < NL; l++) {
        dim3 gproj((6 * DH + 127) / 128, (N + 255) / 256);
        mma_gemm_k<<<gproj, 256>>>(N, 6 * DH, DIN, xcur, DIN,           // 5 (l=0)
                                   wpack + (size_t)l * DIN * 768, 768,
                                   bpack + (size_t)l * 768, qkv, 768, 0);

        if (!decoded) {
            decode_idx_k<<<512, 256>>>(E, N, eiraw, srcA, dstA);
            decoded = true;
        }
        cudaMemsetAsync(maxu_p, 0, 4);
        cudaMemsetAsync(z_p, 0, 4);
        cudaMemsetAsync(aggr, 0, (size_t)N * DH * sizeof(float));

        edge_score_k<<<eblocks, 256>>>(E, srcA, dstA, qkv, score);
        expsum_k<<<1024, 256>>>(E, score);
        edge_msg_k<<<eblocks, 256>>>(E, srcA, dstA, qkv, eattr, score, aggr);

        node_ln1_k<<<N, 128>>>(aggr, qkv, g1 + (size_t)l * DH, be1 + (size_t)l * DH, ss);

        dim3 gff1((DFF + 127) / 128, (N + 255) / 256);
        mma_gemm_k<<<gff1, 256>>>(N, DFF, DH, ss, DH,
                                  W1 + (size_t)l * DH * DFF, DFF,
                                  b1 + (size_t)l * DFF, tbuf, DFF, 1);
        dim3 gff2((DH + 127) / 128, (N + 255) / 256);
        mma_gemm_k<<<gff2, 256>>>(N, DH, DFF, tbuf, DFF,
                                  W2 + (size_t)l * DFF * DH, DH,
                                  b2 + (size_t)l * DH, ss2, DH, 0);

        node_ln2_k<<<N, 128>>>(ss, ss2, g2 + (size_t)l * DH, be2 + (size_t)l * DH, h2);

        dim3 glin((DIN + 127) / 128, (N + 255) / 256);
        mma_gemm_k<<<glin, 256>>>(N, DIN, DH, h2, DH, linW, DIN, linb, x_buf, DIN, 0);
        xcur = x_buf;
    }

    dim3 gfin((DH + 127) / 128, (N + 255) / 256);
    mma_gemm_k<<<gfin, 256>>>(N, DH, DIN, xcur, DIN, lin2W, DH, lin2b,
                              (float*)d_out, DH, 2);
}

// round 7
// speedup vs baseline: 2.2157x; 1.3669x over previous
#include <cuda_runtime.h>
#include <cuda_bf16.h>
#include <math.h>
#include <stdint.h>

#define DIN 1546
#define DH  128
#define DFF 512
#define NL  2

static const int NMAXC = 20000;
static const int EMAXC = 640000;

// ---------------- scratch (device globals; no allocation allowed) ----------
__device__ __align__(16) float g_x    [NMAXC * DIN];
__device__ __align__(16) float g_qkv  [NMAXC * 6 * DH];
__device__ __align__(16) float g_scr  [EMAXC];
__device__ __align__(16) float g_aggr [NMAXC * DH];
__device__ __align__(16) float g_ss   [NMAXC * DH];
__device__ __align__(16) float g_t    [NMAXC * DFF];
__device__ __align__(16) float g_ss2  [NMAXC * DH];
__device__ __align__(16) float g_h2   [NMAXC * DH];
__device__ __align__(16) float g_wpack[NL * DIN * 6 * DH];
__device__ __align__(16) float g_bpack[NL * 6 * DH];
__device__ int g_src[EMAXC];
__device__ int g_dst[EMAXC];
__device__ unsigned g_maxu;
__device__ float    g_Z;
__device__ int      g_is64;

__device__ __forceinline__ unsigned fenc(float f) {
    unsigned u = __float_as_uint(f);
    return (u & 0x80000000u) ? ~u : (u | 0x80000000u);
}
__device__ __forceinline__ float fdec(unsigned u) {
    return __uint_as_float((u & 0x80000000u) ? (u ^ 0x80000000u) : ~u);
}

// ---------------- bf16 split helpers ----------------------------------------
__device__ __forceinline__ uint32_t pack_bf2(__nv_bfloat16 a, __nv_bfloat16 b) {
    __nv_bfloat162 t = __halves2bfloat162(a, b);
    return *reinterpret_cast<uint32_t*>(&t);
}
// split pair (x0,x1) into hi/lo packed bf16x2
__device__ __forceinline__ void split2(float x0, float x1, uint32_t& h, uint32_t& l) {
    __nv_bfloat16 h0 = __float2bfloat16(x0);
    __nv_bfloat16 h1 = __float2bfloat16(x1);
    __nv_bfloat16 l0 = __float2bfloat16(x0 - __bfloat162float(h0));
    __nv_bfloat16 l1 = __float2bfloat16(x1 - __bfloat162float(h1));
    h = pack_bf2(h0, h1);
    l = pack_bf2(l0, l1);
}
__device__ __forceinline__ void mma_bf16(float* c, const uint32_t* a, const uint32_t* b) {
    asm volatile(
        "mma.sync.aligned.m16n8k16.row.col.f32.bf16.bf16.f32 "
        "{%0,%1,%2,%3},{%4,%5,%6,%7},{%8,%9},{%0,%1,%2,%3};"
        : "+f"(c[0]), "+f"(c[1]), "+f"(c[2]), "+f"(c[3])
        : "r"(a[0]), "r"(a[1]), "r"(a[2]), "r"(a[3]), "r"(b[0]), "r"(b[1]));
}

// ---------------- edge-index dtype probe + decode ---------------------------
__global__ void detect_idx_k(const int* __restrict__ raw, int nsamp)
{
    int i = blockIdx.x * blockDim.x + threadIdx.x;
    if (i < nsamp && raw[2 * i + 1] != 0) atomicExch(&g_is64, 0);
}

__global__ void decode_idx_k(int E, int N, const int* __restrict__ raw,
                             int* __restrict__ src, int* __restrict__ dst)
{
    int is64 = g_is64;
    for (int e = blockIdx.x * blockDim.x + threadIdx.x; e < E;
         e += gridDim.x * blockDim.x) {
        int s, d;
        if (is64) {
            s = raw[2 * (size_t)e];
            d = raw[2 * ((size_t)E + e)];
        } else {
            s = raw[e];
            d = raw[(size_t)E + e];
        }
        src[e] = min(max(s, 0), N - 1);
        dst[e] = min(max(d, 0), N - 1);
    }
}

// ---------------- weight/bias packing ----------------------------------------
__global__ void pack_w_k(const float* __restrict__ Wq, const float* __restrict__ Wk,
                         const float* __restrict__ Wv, const float* __restrict__ Wr,
                         const float* __restrict__ Whi, const float* __restrict__ Whj,
                         float* __restrict__ out)
{
    const float* Ws[6] = {Wq, Wk, Wv, Wr, Whi, Whj};
    size_t total = (size_t)NL * DIN * DH;
    for (size_t i = blockIdx.x * (size_t)blockDim.x + threadIdx.x; i < total;
         i += (size_t)gridDim.x * blockDim.x) {
        int c = i % DH;
        int k = (i / DH) % DIN;
        int l = i / ((size_t)DH * DIN);
        size_t obase = (size_t)l * DIN * 768 + (size_t)k * 768 + c;
        size_t ibase = (size_t)l * DIN * DH + (size_t)k * DH + c;
#pragma unroll
        for (int j = 0; j < 6; j++) out[obase + j * DH] = Ws[j][ibase];
    }
}

__global__ void pack_b_k(const float* __restrict__ bq, const float* __restrict__ bk,
                         const float* __restrict__ bv, const float* __restrict__ br,
                         float* __restrict__ out)
{
    int i = threadIdx.x + blockIdx.x * blockDim.x;
    if (i >= NL * 768) return;
    int c = i % 768, l = i / 768;
    int j = c / DH, cc = c % DH;
    float v = 0.f;
    if (j == 0) v = bq[l * DH + cc];
    else if (j == 1) v = bk[l * DH + cc];
    else if (j == 2) v = bv[l * DH + cc];
    else if (j == 3) v = br[l * DH + cc];
    out[i] = v;
}

// ---------------- tensor-core GEMM: 3x bf16-split, BM=256 BN=128 BK=16 -------
// 8 warps (4x2), warp tile 64x64 via m16n8k16.bf16. Fragment-layout smem,
// double-buffered, register prefetch. act: 0 none, 1 relu, 2 leaky(0.01)
__global__ void __launch_bounds__(256, 1)
mma_gemm_k(int M, int Nn, int K,
           const float* __restrict__ A, int lda,
           const float* __restrict__ B, int ldb,
           const float* __restrict__ bias,
           float* __restrict__ C, int ldc, int act)
{
    // [buf][split][tile][lane][reg] (uint32 = bf16x2)
    __shared__ __align__(16) uint32_t Asf[2][2][16][32][4];  // 32 KB
    __shared__ __align__(16) uint32_t Bsf[2][2][16][32][2];  // 16 KB

    const int tid  = threadIdx.x;
    const int lane = tid & 31;
    const int wid  = tid >> 5;
    const int g    = lane >> 2;   // group 0..7
    const int tig  = lane & 3;    // 0..3
    const int warp_m = wid & 3;   // 0..3  (64 rows each)
    const int warp_n = wid >> 2;  // 0..1  (64 cols each)
    const int row0 = blockIdx.y * 256;
    const int col0 = blockIdx.x * 128;

    float acc[4][8][4];
#pragma unroll
    for (int m = 0; m < 4; m++)
#pragma unroll
        for (int n = 0; n < 8; n++)
#pragma unroll
            for (int r = 0; r < 4; r++) acc[m][n][r] = 0.f;

    // per-thread staged loads: A 2 tiles x 8 floats, B 2 tiles x 4 floats
    float pa[2][8], pb[2][4];

    // fragment element coords within a k16 slice (m16n8k16):
    //  A reg r (pair): r0=(g,2tig,2tig+1) r1=(g+8,..) r2=(g,2tig+8,+9) r3=(g+8,+8,+9)
    //  B reg r (pair): r0=(k=2tig,2tig+1; col g) r1=(k=2tig+8,+9; col g)
    auto load_regs = [&](int k0) {
#pragma unroll
        for (int i = 0; i < 2; i++) {
            int mt = wid * 2 + i;
#pragma unroll
            for (int r = 0; r < 4; r++) {
                int rr = row0 + mt * 16 + g + 8 * (r & 1);
                int c0 = k0 + 2 * tig + 8 * (r >> 1);
                bool rok = rr < M;
                const float* Ap = A + (size_t)rr * lda + c0;
                pa[i][r * 2 + 0] = (rok && c0 < K)     ? Ap[0] : 0.f;
                pa[i][r * 2 + 1] = (rok && c0 + 1 < K) ? Ap[1] : 0.f;
            }
        }
#pragma unroll
        for (int i = 0; i < 2; i++) {
            int nt = wid * 2 + i;
            int cc = col0 + nt * 8 + g;
            bool cok = cc < Nn;
#pragma unroll
            for (int r = 0; r < 2; r++) {
                int kk = k0 + 2 * tig + 8 * r;
                pb[i][r * 2 + 0] = (cok && kk < K)     ? B[(size_t)kk * ldb + cc] : 0.f;
                pb[i][r * 2 + 1] = (cok && kk + 1 < K) ? B[(size_t)(kk + 1) * ldb + cc] : 0.f;
            }
        }
    };

    auto store_smem = [&](int buf) {
#pragma unroll
        for (int i = 0; i < 2; i++) {
            int mt = wid * 2 + i;
            uint4 h, l;
            split2(pa[i][0], pa[i][1], h.x, l.x);
            split2(pa[i][2], pa[i][3], h.y, l.y);
            split2(pa[i][4], pa[i][5], h.z, l.z);
            split2(pa[i][6], pa[i][7], h.w, l.w);
            *(uint4*)&Asf[buf][0][mt][lane][0] = h;
            *(uint4*)&Asf[buf][1][mt][lane][0] = l;
        }
#pragma unroll
        for (int i = 0; i < 2; i++) {
            int nt = wid * 2 + i;
            uint2 h, l;
            split2(pb[i][0], pb[i][1], h.x, l.x);
            split2(pb[i][2], pb[i][3], h.y, l.y);
            *(uint2*)&Bsf[buf][0][nt][lane][0] = h;
            *(uint2*)&Bsf[buf][1][nt][lane][0] = l;
        }
    };

    auto compute = [&](int buf) {
        uint32_t ah[4][4], al[4][4];
#pragma unroll
        for (int m = 0; m < 4; m++) {
            int mt = warp_m * 4 + m;
            uint4 t = *(const uint4*)&Asf[buf][0][mt][lane][0];
            ah[m][0] = t.x; ah[m][1] = t.y; ah[m][2] = t.z; ah[m][3] = t.w;
            uint4 u = *(const uint4*)&Asf[buf][1][mt][lane][0];
            al[m][0] = u.x; al[m][1] = u.y; al[m][2] = u.z; al[m][3] = u.w;
        }
#pragma unroll
        for (int n = 0; n < 8; n++) {
            int nt = warp_n * 8 + n;
            uint32_t bh[2], bl[2];
            uint2 t = *(const uint2*)&Bsf[buf][0][nt][lane][0];
            bh[0] = t.x; bh[1] = t.y;
            uint2 u = *(const uint2*)&Bsf[buf][1][nt][lane][0];
            bl[0] = u.x; bl[1] = u.y;
#pragma unroll
            for (int m = 0; m < 4; m++) {
                mma_bf16(acc[m][n], ah[m], bh);
                mma_bf16(acc[m][n], ah[m], bl);
                mma_bf16(acc[m][n], al[m], bh);
            }
        }
    };

    load_regs(0);
    store_smem(0);
    __syncthreads();

    int buf = 0;
    for (int k0 = 0; k0 < K; k0 += 16) {
        int kn = k0 + 16;
        bool more = kn < K;
        if (more) load_regs(kn);
        compute(buf);
        if (more) {
            store_smem(buf ^ 1);
            __syncthreads();
            buf ^= 1;
        }
    }

    // epilogue: c0(g, 2tig) c1(g, 2tig+1) c2(g+8, 2tig) c3(g+8, 2tig+1)
#pragma unroll
    for (int m = 0; m < 4; m++) {
        int rb = row0 + warp_m * 64 + m * 16 + g;
#pragma unroll
        for (int n = 0; n < 8; n++) {
            int cb = col0 + warp_n * 64 + n * 8 + tig * 2;
#pragma unroll
            for (int h = 0; h < 2; h++) {
                int rr = rb + h * 8;
                if (rr >= M) continue;
#pragma unroll
                for (int q = 0; q < 2; q++) {
                    int cc = cb + q;
                    if (cc >= Nn) continue;
                    float v = acc[m][n][h * 2 + q] + (bias ? bias[cc] : 0.f);
                    if (act == 1) v = fmaxf(v, 0.f);
                    else if (act == 2) v = v > 0.f ? v : 0.01f * v;
                    C[(size_t)rr * ldc + cc] = v;
                }
            }
        }
    }
}

// ---------------- edge pass 1 -------------------------------------------------
__global__ void edge_score_k(int E, const int* __restrict__ srcA,
                             const int* __restrict__ dstA,
                             const float* __restrict__ qkv,
                             float* __restrict__ score)
{
    int warp  = (blockIdx.x * blockDim.x + threadIdx.x) >> 5;
    int lane  = threadIdx.x & 31;
    int wloc  = threadIdx.x >> 5;
    __shared__ float sm[8];
    float d = -3.4e38f;
    if (warp < E) {
        int src = srcA[warp];
        int dst = dstA[warp];
        float4 q = *(const float4*)(qkv + (size_t)dst * 768 + lane * 4);
        float4 k = *(const float4*)(qkv + (size_t)src * 768 + 128 + lane * 4);
        d = q.x * k.x + q.y * k.y + q.z * k.z + q.w * k.w;
#pragma unroll
        for (int o = 16; o; o >>= 1) d += __shfl_xor_sync(0xffffffffu, d, o);
        if (lane == 0) score[warp] = d;
    }
    if (lane == 0) sm[wloc] = d;
    __syncthreads();
    if (threadIdx.x == 0) {
        float m = sm[0];
        int nw = blockDim.x >> 5;
        for (int i = 1; i < nw; i++) m = fmaxf(m, sm[i]);
        atomicMax(&g_maxu, fenc(m));
    }
}

// ---------------- edge pass 2 -------------------------------------------------
__global__ void expsum_k(int E, float* __restrict__ score)
{
    float gmax = fdec(g_maxu);
    float s = 0.f;
    for (int i = blockIdx.x * blockDim.x + threadIdx.x; i < E;
         i += gridDim.x * blockDim.x) {
        float p = expf(score[i] - gmax);
        score[i] = p;
        s += p;
    }
#pragma unroll
    for (int o = 16; o; o >>= 1) s += __shfl_xor_sync(0xffffffffu, s, o);
    __shared__ float sm[8];
    int w = threadIdx.x >> 5, l = threadIdx.x & 31;
    if (l == 0) sm[w] = s;
    __syncthreads();
    if (threadIdx.x == 0) {
        float t = 0.f;
        int nw = blockDim.x >> 5;
        for (int i = 0; i < nw; i++) t += sm[i];
        atomicAdd(&g_Z, t);
    }
}

// ---------------- edge pass 3 -------------------------------------------------
__global__ void edge_msg_k(int E, const int* __restrict__ srcA,
                           const int* __restrict__ dstA,
                           const float* __restrict__ qkv,
                           const float* __restrict__ eattr,
                           const float* __restrict__ score,
                           float* __restrict__ aggr)
{
    int warp = (blockIdx.x * blockDim.x + threadIdx.x) >> 5;
    int lane = threadIdx.x & 31;
    if (warp >= E) return;
    int src = srcA[warp];
    int dst = dstA[warp];
    float p = __ldg(score + warp);

    float4 v  = *(const float4*)(qkv + (size_t)src * 768 + 256 + lane * 4);
    float4 hi = *(const float4*)(qkv + (size_t)src * 768 + 512 + lane * 4);
    float4 hj = *(const float4*)(qkv + (size_t)dst * 768 + 640 + lane * 4);
    float4 ea = *(const float4*)(eattr + (size_t)warp * 128 + lane * 4);

    float m0 = p * v.x * (1.f / (1.f + expf(-(ea.x + hi.x + hj.x))));
    float m1 = p * v.y * (1.f / (1.f + expf(-(ea.y + hi.y + hj.y))));
    float m2 = p * v.z * (1.f / (1.f + expf(-(ea.z + hi.z + hj.z))));
    float m3 = p * v.w * (1.f / (1.f + expf(-(ea.w + hi.w + hj.w))));

    float* out = aggr + (size_t)dst * 128 + lane * 4;
    atomicAdd(out + 0, m0);
    atomicAdd(out + 1, m1);
    atomicAdd(out + 2, m2);
    atomicAdd(out + 3, m3);
}

// ---------------- node LayerNorm kernels ---------------------------------------
__device__ __forceinline__ void block_meanvar_128(float h, float& mean, float& var)
{
    float s = h, s2 = h * h;
#pragma unroll
    for (int o = 16; o; o >>= 1) {
        s  += __shfl_xor_sync(0xffffffffu, s, o);
        s2 += __shfl_xor_sync(0xffffffffu, s2, o);
    }
    __shared__ float sm[8];
    int w = threadIdx.x >> 5, l = threadIdx.x & 31;
    if (l == 0) { sm[w] = s; sm[4 + w] = s2; }
    __syncthreads();
    float ts  = sm[0] + sm[1] + sm[2] + sm[3];
    float ts2 = sm[4] + sm[5] + sm[6] + sm[7];
    mean = ts * (1.f / 128.f);
    var  = ts2 * (1.f / 128.f) - mean * mean;
}

__global__ void node_ln1_k(const float* __restrict__ aggr,
                           const float* __restrict__ qkv,
                           const float* __restrict__ gam,
                           const float* __restrict__ bet,
                           float* __restrict__ out)
{
    int n = blockIdx.x, d = threadIdx.x;
    float h = aggr[(size_t)n * 128 + d] / g_Z + qkv[(size_t)n * 768 + 384 + d];
    float mean, var;
    block_meanvar_128(h, mean, var);
    out[(size_t)n * 128 + d] = (h - mean) * rsqrtf(var + 1e-5f) * gam[d] + bet[d];
}

__global__ void node_ln2_k(const float* __restrict__ ss,
                           const float* __restrict__ ss2,
                           const float* __restrict__ gam,
                           const float* __restrict__ bet,
                           float* __restrict__ out)
{
    int n = blockIdx.x, d = threadIdx.x;
    float h = ss[(size_t)n * 128 + d] + ss2[(size_t)n * 128 + d];
    float mean, var;
    block_meanvar_128(h, mean, var);
    out[(size_t)n * 128 + d] = (h - mean) * rsqrtf(var + 1e-5f) * gam[d] + bet[d];
}

// ---------------- host orchestration ---------------------------------------
extern "C" void kernel_launch(void* const* d_in, const int* in_sizes, int n_in,
                              void* d_out, int out_size)
{
    const float* x_in  = (const float*)d_in[0];
    const int*   eiraw = (const int*)d_in[1];
    const float* eattr = (const float*)d_in[2];
    const float* Wq  = (const float*)d_in[3];
    const float* bq  = (const float*)d_in[4];
    const float* Wk  = (const float*)d_in[5];
    const float* bk  = (const float*)d_in[6];
    const float* Wv  = (const float*)d_in[7];
    const float* bv  = (const float*)d_in[8];
    const float* Wr  = (const float*)d_in[9];
    const float* br  = (const float*)d_in[10];
    const float* Whi = (const float*)d_in[11];
    const float* Whj = (const float*)d_in[12];
    const float* W1  = (const float*)d_in[13];
    const float* b1  = (const float*)d_in[14];
    const float* W2  = (const float*)d_in[15];
    const float* b2  = (const float*)d_in[16];
    const float* g1  = (const float*)d_in[17];
    const float* be1 = (const float*)d_in[18];
    const float* g2  = (const float*)d_in[19];
    const float* be2 = (const float*)d_in[20];
    const float* linW  = (const float*)d_in[21];
    const float* linb  = (const float*)d_in[22];
    const float* lin2W = (const float*)d_in[23];
    const float* lin2b = (const float*)d_in[24];

    const int N = in_sizes[0] / DIN;
    const int E = in_sizes[1] / 2;

    float *x_buf, *qkv, *score, *aggr, *ss, *tbuf, *ss2, *h2, *wpack, *bpack;
    int *srcA, *dstA;
    void* p;
    cudaGetSymbolAddress(&p, g_x);     x_buf = (float*)p;
    cudaGetSymbolAddress(&p, g_qkv);   qkv   = (float*)p;
    cudaGetSymbolAddress(&p, g_scr);   score = (float*)p;
    cudaGetSymbolAddress(&p, g_aggr);  aggr  = (float*)p;
    cudaGetSymbolAddress(&p, g_ss);    ss    = (float*)p;
    cudaGetSymbolAddress(&p, g_t);     tbuf  = (float*)p;
    cudaGetSymbolAddress(&p, g_ss2);   ss2   = (float*)p;
    cudaGetSymbolAddress(&p, g_h2);    h2    = (float*)p;
    cudaGetSymbolAddress(&p, g_wpack); wpack = (float*)p;
    cudaGetSymbolAddress(&p, g_bpack); bpack = (float*)p;
    cudaGetSymbolAddress(&p, g_src);   srcA  = (int*)p;
    cudaGetSymbolAddress(&p, g_dst);   dstA  = (int*)p;
    void *maxu_p, *z_p, *is64_p;
    cudaGetSymbolAddress(&maxu_p, g_maxu);
    cudaGetSymbolAddress(&z_p, g_Z);
    cudaGetSymbolAddress(&is64_p, g_is64);

    // prologue ordered so the 5th launch is the layer-0 projection GEMM
    cudaMemsetAsync(is64_p, 1, 4);                                      // 1
    int nsamp = E < 65536 ? E : 65536;
    detect_idx_k<<<(nsamp + 255) / 256, 256>>>(eiraw, nsamp);           // 2
    pack_w_k<<<1024, 256>>>(Wq, Wk, Wv, Wr, Whi, Whj, wpack);           // 3
    pack_b_k<<<(NL * 768 + 255) / 256, 256>>>(bq, bk, bv, br, bpack);   // 4

    const float* xcur = x_in;
    const int eblocks = (E * 32 + 255) / 256;
    bool decoded = false;

    for (int l = 0; l < NL; l++) {
        dim3 gproj((6 * DH + 127) / 128, (N + 255) / 256);
        mma_gemm_k<<<gproj, 256>>>(N, 6 * DH, DIN, xcur, DIN,           // 5 (l=0)
                                   wpack + (size_t)l * DIN * 768, 768,
                                   bpack + (size_t)l * 768, qkv, 768, 0);

        if (!decoded) {
            decode_idx_k<<<512, 256>>>(E, N, eiraw, srcA, dstA);
            decoded = true;
        }
        cudaMemsetAsync(maxu_p, 0, 4);
        cudaMemsetAsync(z_p, 0, 4);
        cudaMemsetAsync(aggr, 0, (size_t)N * DH * sizeof(float));

        edge_score_k<<<eblocks, 256>>>(E, srcA, dstA, qkv, score);
        expsum_k<<<1024, 256>>>(E, score);
        edge_msg_k<<<eblocks, 256>>>(E, srcA, dstA, qkv, eattr, score, aggr);

        node_ln1_k<<<N, 128>>>(aggr, qkv, g1 + (size_t)l * DH, be1 + (size_t)l * DH, ss);

        dim3 gff1((DFF + 127) / 128, (N + 255) / 256);
        mma_gemm_k<<<gff1, 256>>>(N, DFF, DH, ss, DH,
                                  W1 + (size_t)l * DH * DFF, DFF,
                                  b1 + (size_t)l * DFF, tbuf, DFF, 1);
        dim3 gff2((DH + 127) / 128, (N + 255) / 256);
        mma_gemm_k<<<gff2, 256>>>(N, DH, DFF, tbuf, DFF,
                                  W2 + (size_t)l * DFF * DH, DH,
                                  b2 + (size_t)l * DH, ss2, DH, 0);

        node_ln2_k<<<N, 128>>>(ss, ss2, g2 + (size_t)l * DH, be2 + (size_t)l * DH, h2);

        dim3 glin((DIN + 127) / 128, (N + 255) / 256);
        mma_gemm_k<<<glin, 256>>>(N, DIN, DH, h2, DH, linW, DIN, linb, x_buf, DIN, 0);
        xcur = x_buf;
    }

    dim3 gfin((DH + 127) / 128, (N + 255) / 256);
    mma_gemm_k<<<gfin, 256>>>(N, DH, DIN, xcur, DIN, lin2W, DH, lin2b,
                              (float*)d_out, DH, 2);
}